// round 6
// baseline (speedup 1.0000x reference)
#include <cuda_runtime.h>
#include <cstdint>

#define BB 8
#define SS 1024
#define DD 512
#define HH 8

// ---------------- device scratch (static, allocation-free) ----------------
__device__ __align__(256) float g_q[BB*HH*SS*DD];        // [B,H,S,E]
__device__ __align__(256) float g_k[BB*HH*SS*DD];        // [B,H,S,E]
__device__ __align__(256) float g_vt[BB*HH*DD*SS];       // [B,H,E,S]  (V transposed)
__device__ __align__(256) float g_sc[(size_t)BB*HH*SS*SS]; // [B,H,S,S] scores / probs
__device__ __align__(256) float g_hcat[BB*SS*HH*DD];     // [B,S,H*E]
__device__ __align__(256) float g_xr[BB*SS*DD];          // tf32-rounded X
__device__ __align__(256) float g_wvr[HH*DD*DD];         // tf32-rounded Wv
__device__ __align__(256) float g_wor[DD*HH*DD];         // tf32-rounded Wo

// ---------------- small helpers ----------------
__device__ __forceinline__ unsigned smem_u32(const void* p) {
    return (unsigned)__cvta_generic_to_shared(p);
}
__device__ __forceinline__ void cp16(void* dst, const void* src) {
    asm volatile("cp.async.cg.shared.global [%0], [%1], 16;\n"
                 :: "r"(smem_u32(dst)), "l"(src));
}
__device__ __forceinline__ float tf32_rna(float x) {
    uint32_t y;
    asm("cvt.rna.tf32.f32 %0, %1;" : "=r"(y) : "f"(x));
    return __uint_as_float(y);
}

// ---------------- shared TF32 GEMM mainloop ----------------
// C[128,128] += A[128,K] * B[128,K]^T  (both operands row-major, K contiguous)
// Ag/Bg already offset to (m0, n0). smem: 2 stages x (A 4096 + B 4096 floats).
template<int KT>
__device__ __forceinline__ void gemm_main(const float* __restrict__ Ag,
                                          const float* __restrict__ Bg,
                                          float* sm, float (&acc)[4][4][4])
{
    const int K = KT * 32;
    const int tid  = threadIdx.x;
    const int lane = tid & 31;
    const int warp = tid >> 5;
    const int wm = (warp & 1) * 64;   // 2 warps along M
    const int wn = (warp >> 1) * 32;  // 4 warps along N

#pragma unroll
    for (int mi = 0; mi < 4; mi++)
#pragma unroll
        for (int ni = 0; ni < 4; ni++)
#pragma unroll
            for (int r = 0; r < 4; r++) acc[mi][ni][r] = 0.f;

    const int srow = tid >> 3;   // 0..31
    const int sch  = tid & 7;    // 16B chunk 0..7

    auto stage = [&](int s, int kt) {
        float* sA = sm + s * 8192;
        float* sB = sA + 4096;
        const float* ap = Ag + (size_t)srow * K + kt * 32 + sch * 4;
        const float* bp = Bg + (size_t)srow * K + kt * 32 + sch * 4;
#pragma unroll
        for (int i = 0; i < 4; i++) {
            int r = srow + i * 32;
            int sw = (sch ^ (r & 7)) << 2;
            cp16(sA + r * 32 + sw, ap + (size_t)i * 32 * K);
            cp16(sB + r * 32 + sw, bp + (size_t)i * 32 * K);
        }
        asm volatile("cp.async.commit_group;\n");
    };

    stage(0, 0);

#pragma unroll 1
    for (int kt = 0; kt < KT; kt++) {
        if (kt + 1 < KT) {
            stage((kt + 1) & 1, kt + 1);
            asm volatile("cp.async.wait_group 1;\n");
        } else {
            asm volatile("cp.async.wait_group 0;\n");
        }
        __syncthreads();

        const float* sA = sm + (kt & 1) * 8192;
        const float* sB = sA + 4096;

#pragma unroll
        for (int ks = 0; ks < 4; ks++) {
            uint32_t a[4][4];
#pragma unroll
            for (int mi = 0; mi < 4; mi++) {
                int r  = wm + mi * 16 + (lane & 15);
                int ch = 2 * ks + (lane >> 4);
                unsigned ad = smem_u32(sA + r * 32 + ((ch ^ (r & 7)) << 2));
                asm volatile("ldmatrix.sync.aligned.m8n8.x4.shared.b16 {%0,%1,%2,%3}, [%4];"
                             : "=r"(a[mi][0]), "=r"(a[mi][1]), "=r"(a[mi][2]), "=r"(a[mi][3])
                             : "r"(ad));
            }
            uint32_t b[4][2];
#pragma unroll
            for (int nj = 0; nj < 2; nj++) {
                int nr = wn + nj * 16 + ((lane >> 4) << 3) + (lane & 7);
                int ch = 2 * ks + ((lane >> 3) & 1);
                unsigned ad = smem_u32(sB + nr * 32 + ((ch ^ (nr & 7)) << 2));
                uint32_t r0, r1, r2, r3;
                asm volatile("ldmatrix.sync.aligned.m8n8.x4.shared.b16 {%0,%1,%2,%3}, [%4];"
                             : "=r"(r0), "=r"(r1), "=r"(r2), "=r"(r3) : "r"(ad));
                b[nj*2][0] = r0;  b[nj*2][1] = r1;
                b[nj*2+1][0] = r2; b[nj*2+1][1] = r3;
            }
#pragma unroll
            for (int mi = 0; mi < 4; mi++)
#pragma unroll
                for (int ni = 0; ni < 4; ni++) {
                    asm volatile(
                        "mma.sync.aligned.m16n8k8.row.col.f32.tf32.tf32.f32 "
                        "{%0,%1,%2,%3}, {%4,%5,%6,%7}, {%8,%9}, {%0,%1,%2,%3};"
                        : "+f"(acc[mi][ni][0]), "+f"(acc[mi][ni][1]),
                          "+f"(acc[mi][ni][2]), "+f"(acc[mi][ni][3])
                        : "r"(a[mi][0]), "r"(a[mi][1]), "r"(a[mi][2]), "r"(a[mi][3]),
                          "r"(b[ni][0]), "r"(b[ni][1]));
                }
        }
        __syncthreads();
    }
}

// element (mi,ni,r) -> local (row,col) within 128x128 tile
#define EPI_ROW(wm, mi, r)  ((wm) + (mi)*16 + (lane >> 2) + (((r) >> 1) << 3))
#define EPI_COL(wn, ni, r)  ((wn) + (ni)*8 + ((lane & 3) << 1) + ((r) & 1))

// ---------------- phase 0: pre-round precision-critical inputs ----------------
__global__ void k_round(const float* __restrict__ X, const float* __restrict__ Wv,
                        const float* __restrict__ Wo)
{
    const int NX = BB*SS*DD, NW = HH*DD*DD, NO = DD*HH*DD;
    int stride = gridDim.x * blockDim.x;
    int i0 = blockIdx.x * blockDim.x + threadIdx.x;
    for (int i = i0; i < NX; i += stride) g_xr[i]  = tf32_rna(X[i]);
    for (int i = i0; i < NW; i += stride) g_wvr[i] = tf32_rna(Wv[i]);
    for (int i = i0; i < NO; i += stride) g_wor[i] = tf32_rna(Wo[i]);
}

// ---------------- phase 1: QKV projections ----------------
// grid: (64, 4, 24)  z = proj*8 + h;  C[8192,512] = X @ W_h^T + b
__global__ void __launch_bounds__(256, 1) k_qkv(
    const float* __restrict__ Wq, const float* __restrict__ Wk,
    const float* __restrict__ bq, const float* __restrict__ bk,
    const float* __restrict__ bv)
{
    extern __shared__ float sm[];
    const int m0 = blockIdx.x * 128, n0 = blockIdx.y * 128;
    const int z = blockIdx.z, proj = z >> 3, h = z & 7;

    const float* Bmat = (proj == 0 ? Wq : proj == 1 ? Wk : g_wvr) + (size_t)h * DD * DD;
    float acc[4][4][4];
    gemm_main<16>(g_xr + (size_t)m0 * DD, Bmat + (size_t)n0 * DD, sm, acc);

    const int lane = threadIdx.x & 31, warp = threadIdx.x >> 5;
    const int wm = (warp & 1) * 64, wn = (warp >> 1) * 32;
    const float* bias = (proj == 0 ? bq : proj == 1 ? bk : bv) + h * DD;

    if (proj < 2) {
        float* out = (proj == 0 ? g_q : g_k);
#pragma unroll
        for (int mi = 0; mi < 4; mi++)
#pragma unroll
            for (int ni = 0; ni < 4; ni++)
#pragma unroll
                for (int r = 0; r < 4; r++) {
                    int row = m0 + EPI_ROW(wm, mi, r);
                    int col = n0 + EPI_COL(wn, ni, r);
                    int b = row >> 10, s = row & 1023;
                    out[(((size_t)(b*HH + h)*SS + s) * DD) + col] = acc[mi][ni][r] + bias[col];
                }
    } else {
        // V: transpose through smem, store rounded into g_vt[b,h,e,s]
        __syncthreads();
        float* T = sm;  // 128 x 132
#pragma unroll
        for (int mi = 0; mi < 4; mi++)
#pragma unroll
            for (int ni = 0; ni < 4; ni++)
#pragma unroll
                for (int r = 0; r < 4; r++) {
                    int rl = EPI_ROW(wm, mi, r);
                    int cl = EPI_COL(wn, ni, r);
                    T[cl * 132 + rl] = tf32_rna(acc[mi][ni][r] + bias[n0 + cl]);
                }
        __syncthreads();
        const int b  = m0 >> 10;      // batch of this tile
        const int s0 = m0 & 1023;     // within-batch sequence offset  (THE FIX)
        float* base = g_vt + (size_t)(b*HH + h) * DD * SS;
        for (int it = threadIdx.x; it < 128 * 32; it += 256) {
            int er = it >> 5;
            int cb = (it & 31) << 2;
            float4 v = make_float4(T[er*132 + cb], T[er*132 + cb + 1],
                                   T[er*132 + cb + 2], T[er*132 + cb + 3]);
            *(float4*)(base + (size_t)(n0 + er) * SS + s0 + cb) = v;
        }
    }
}

// ---------------- phase 2: scores = Q K^T / D^2 ----------------
// grid: (8, 8, 64)
__global__ void __launch_bounds__(256, 1) k_scores()
{
    extern __shared__ float sm[];
    const int m0 = blockIdx.x * 128, n0 = blockIdx.y * 128, z = blockIdx.z;
    const float* A = g_q + (size_t)z * SS * DD + (size_t)m0 * DD;
    const float* B = g_k + (size_t)z * SS * DD + (size_t)n0 * DD;
    float acc[4][4][4];
    gemm_main<16>(A, B, sm, acc);

    float* C = g_sc + (size_t)z * SS * SS;
    const float scl = 1.0f / 262144.0f;  // 1 / 512^2
    const int lane = threadIdx.x & 31, warp = threadIdx.x >> 5;
    const int wm = (warp & 1) * 64, wn = (warp >> 1) * 32;
#pragma unroll
    for (int mi = 0; mi < 4; mi++)
#pragma unroll
        for (int ni = 0; ni < 4; ni++)
#pragma unroll
            for (int r = 0; r < 4; r++) {
                int row = m0 + EPI_ROW(wm, mi, r);
                int col = n0 + EPI_COL(wn, ni, r);
                C[(size_t)row * SS + col] = acc[mi][ni][r] * scl;
            }
}

// ---------------- phase 3: row softmax (in place), output rounded to tf32 ----------------
// grid: 8192 blocks x 256 thr; one warp per row of 1024
__global__ void k_softmax()
{
    const int row  = blockIdx.x * 8 + (threadIdx.x >> 5);
    const int lane = threadIdx.x & 31;
    float4* p4 = (float4*)(g_sc + (size_t)row * SS);

    float v[32];
#pragma unroll
    for (int i = 0; i < 8; i++) {
        float4 t = p4[lane + i * 32];
        v[i*4] = t.x; v[i*4+1] = t.y; v[i*4+2] = t.z; v[i*4+3] = t.w;
    }
    float m = v[0];
#pragma unroll
    for (int i = 1; i < 32; i++) m = fmaxf(m, v[i]);
#pragma unroll
    for (int o = 16; o > 0; o >>= 1) m = fmaxf(m, __shfl_xor_sync(0xffffffffu, m, o));
    float s = 0.f;
#pragma unroll
    for (int i = 0; i < 32; i++) { v[i] = __expf(v[i] - m); s += v[i]; }
#pragma unroll
    for (int o = 16; o > 0; o >>= 1) s += __shfl_xor_sync(0xffffffffu, s, o);
    float inv = 1.0f / s;
#pragma unroll
    for (int i = 0; i < 8; i++) {
        float4 t;
        t.x = tf32_rna(v[i*4]   * inv);
        t.y = tf32_rna(v[i*4+1] * inv);
        t.z = tf32_rna(v[i*4+2] * inv);
        t.w = tf32_rna(v[i*4+3] * inv);
        p4[lane + i * 32] = t;
    }
}

// ---------------- phase 4: H = P V  -> hcat ----------------
// grid: (8, 4, 64)
__global__ void __launch_bounds__(256, 1) k_pv()
{
    extern __shared__ float sm[];
    const int m0 = blockIdx.x * 128, n0 = blockIdx.y * 128, z = blockIdx.z;
    const float* A = g_sc + (size_t)z * SS * SS + (size_t)m0 * SS;  // P rows, K=1024
    const float* B = g_vt + (size_t)z * DD * SS + (size_t)n0 * SS;  // V^T rows e
    float acc[4][4][4];
    gemm_main<32>(A, B, sm, acc);

    const int b = z >> 3, h = z & 7;
    const int lane = threadIdx.x & 31, warp = threadIdx.x >> 5;
    const int wm = (warp & 1) * 64, wn = (warp >> 1) * 32;
#pragma unroll
    for (int mi = 0; mi < 4; mi++)
#pragma unroll
        for (int ni = 0; ni < 4; ni++)
#pragma unroll
            for (int r = 0; r < 4; r++) {
                int s_ = m0 + EPI_ROW(wm, mi, r);
                int e  = n0 + EPI_COL(wn, ni, r);
                g_hcat[((size_t)(b*SS + s_)) * (HH*DD) + h*DD + e] = tf32_rna(acc[mi][ni][r]);
            }
}

// ---------------- phase 5: out = Hcat Wo^T + bo ----------------
// grid: (64, 4)
__global__ void __launch_bounds__(256, 1) k_out(const float* __restrict__ bo,
                                                float* __restrict__ out)
{
    extern __shared__ float sm[];
    const int m0 = blockIdx.x * 128, n0 = blockIdx.y * 128;
    const float* A = g_hcat + (size_t)m0 * (HH*DD);   // K = 4096
    const float* B = g_wor  + (size_t)n0 * (HH*DD);
    float acc[4][4][4];
    gemm_main<128>(A, B, sm, acc);

    const int lane = threadIdx.x & 31, warp = threadIdx.x >> 5;
    const int wm = (warp & 1) * 64, wn = (warp >> 1) * 32;
#pragma unroll
    for (int mi = 0; mi < 4; mi++)
#pragma unroll
        for (int ni = 0; ni < 4; ni++)
#pragma unroll
            for (int r = 0; r < 4; r++) {
                int row = m0 + EPI_ROW(wm, mi, r);
                int col = n0 + EPI_COL(wn, ni, r);
                out[(size_t)row * DD + col] = acc[mi][ni][r] + bo[col];
            }
}

// ---------------- host launcher ----------------
extern "C" void kernel_launch(void* const* d_in, const int* in_sizes, int n_in,
                              void* d_out, int out_size)
{
    // dict order confirmed by rounds 2-3 equivalence: X, Wq, bq, Wk, bk, Wv, bv, Wo, bo
    const float* X  = (const float*)d_in[0];
    const float* Wq = (const float*)d_in[1];
    const float* bq = (const float*)d_in[2];
    const float* Wk = (const float*)d_in[3];
    const float* bk = (const float*)d_in[4];
    const float* Wv = (const float*)d_in[5];
    const float* bv = (const float*)d_in[6];
    const float* Wo = (const float*)d_in[7];
    const float* bo = (const float*)d_in[8];
    float* out = (float*)d_out;

    cudaFuncSetAttribute(k_qkv,    cudaFuncAttributeMaxDynamicSharedMemorySize, 69632);
    cudaFuncSetAttribute(k_scores, cudaFuncAttributeMaxDynamicSharedMemorySize, 65536);
    cudaFuncSetAttribute(k_pv,     cudaFuncAttributeMaxDynamicSharedMemorySize, 65536);
    cudaFuncSetAttribute(k_out,    cudaFuncAttributeMaxDynamicSharedMemorySize, 65536);

    k_round<<<4096, 256>>>(X, Wv, Wo);
    k_qkv<<<dim3(64, 4, 24), 256, 69632>>>(Wq, Wk, bq, bk, bv);
    k_scores<<<dim3(8, 8, 64), 256, 65536>>>();
    k_softmax<<<8192, 256>>>();
    k_pv<<<dim3(8, 4, 64), 256, 65536>>>();
    k_out<<<dim3(64, 4), 256, 65536>>>(bo, out);
}

// round 7
// speedup vs baseline: 1.6776x; 1.6776x over previous
#include <cuda_runtime.h>
#include <cuda_fp16.h>
#include <cstdint>

#define BB 8
#define SS 1024
#define DD 512
#define HH 8

// ---------------- device scratch (static, allocation-free) ----------------
__device__ __align__(256) __half g_xh [BB*SS*DD];           // fp16 X
__device__ __align__(256) __half g_wqh[HH*DD*DD];
__device__ __align__(256) __half g_wkh[HH*DD*DD];
__device__ __align__(256) __half g_wvh[HH*DD*DD];
__device__ __align__(256) __half g_woh[DD*HH*DD];
__device__ __align__(256) __half g_qh [BB*HH*SS*DD];        // [B,H,S,E]
__device__ __align__(256) __half g_kh [BB*HH*SS*DD];        // [B,H,S,E]
__device__ __align__(256) __half g_vth[BB*HH*DD*SS];        // [B,H,E,S]
__device__ __align__(256) __half g_sch[(size_t)BB*HH*SS*SS];// [B,H,S,S] raw scores -> P
__device__ __align__(256) __half g_hh [BB*SS*HH*DD];        // [B,S,H*E]

// ---------------- helpers ----------------
__device__ __forceinline__ unsigned smem_u32(const void* p) {
    return (unsigned)__cvta_generic_to_shared(p);
}
__device__ __forceinline__ void cp16(void* dst, const void* src) {
    asm volatile("cp.async.cg.shared.global [%0], [%1], 16;\n"
                 :: "r"(smem_u32(dst)), "l"(src));
}

// ---------------- fp16 GEMM mainloop ----------------
// C[128,128] += A[128,K] * B[128,K]^T, fp16 operands (row-major, K contiguous),
// fp32 accumulate. K-tile = 64 halves (128B rows, XOR-swizzled).
// smem: 2 stages x (A 128x64 + B 128x64 halves) = 64KB.
template<int KT>   // KT = K/64
__device__ __forceinline__ void gemm_h(const __half* __restrict__ Ag,
                                       const __half* __restrict__ Bg,
                                       __half* sm, float (&acc)[4][4][4])
{
    const int K = KT * 64;
    const int tid  = threadIdx.x;
    const int lane = tid & 31;
    const int warp = tid >> 5;
    const int wm = (warp & 1) * 64;   // 2 warps along M
    const int wn = (warp >> 1) * 32;  // 4 warps along N

#pragma unroll
    for (int mi = 0; mi < 4; mi++)
#pragma unroll
        for (int ni = 0; ni < 4; ni++)
#pragma unroll
            for (int r = 0; r < 4; r++) acc[mi][ni][r] = 0.f;

    const int srow = tid >> 3;   // 0..31
    const int sch  = tid & 7;    // 16B chunk within 128B row

    auto stage = [&](int s, int kt) {
        __half* sA = sm + s * (2 * 128 * 64);
        __half* sB = sA + 128 * 64;
        const __half* ap = Ag + (size_t)srow * K + kt * 64 + sch * 8;
        const __half* bp = Bg + (size_t)srow * K + kt * 64 + sch * 8;
#pragma unroll
        for (int i = 0; i < 4; i++) {
            int r = srow + i * 32;
            int sw = (sch ^ (r & 7)) * 8;         // halves
            cp16(sA + r * 64 + sw, ap + (size_t)i * 32 * K);
            cp16(sB + r * 64 + sw, bp + (size_t)i * 32 * K);
        }
        asm volatile("cp.async.commit_group;\n");
    };

    stage(0, 0);

#pragma unroll 1
    for (int kt = 0; kt < KT; kt++) {
        if (kt + 1 < KT) {
            stage((kt + 1) & 1, kt + 1);
            asm volatile("cp.async.wait_group 1;\n");
        } else {
            asm volatile("cp.async.wait_group 0;\n");
        }
        __syncthreads();

        const __half* sA = sm + (kt & 1) * (2 * 128 * 64);
        const __half* sB = sA + 128 * 64;

#pragma unroll
        for (int ks = 0; ks < 4; ks++) {          // 4 x k16 per 64-tile
            uint32_t a[4][4];
#pragma unroll
            for (int mi = 0; mi < 4; mi++) {
                int r  = wm + mi * 16 + (lane & 15);
                int ch = 2 * ks + (lane >> 4);
                unsigned ad = smem_u32(sA + r * 64 + ((ch ^ (r & 7)) * 8));
                asm volatile("ldmatrix.sync.aligned.m8n8.x4.shared.b16 {%0,%1,%2,%3}, [%4];"
                             : "=r"(a[mi][0]), "=r"(a[mi][1]), "=r"(a[mi][2]), "=r"(a[mi][3])
                             : "r"(ad));
            }
            uint32_t b[4][2];
#pragma unroll
            for (int nj = 0; nj < 2; nj++) {
                int nr = wn + nj * 16 + ((lane >> 4) << 3) + (lane & 7);
                int ch = 2 * ks + ((lane >> 3) & 1);
                unsigned ad = smem_u32(sB + nr * 64 + ((ch ^ (nr & 7)) * 8));
                uint32_t r0, r1, r2, r3;
                asm volatile("ldmatrix.sync.aligned.m8n8.x4.shared.b16 {%0,%1,%2,%3}, [%4];"
                             : "=r"(r0), "=r"(r1), "=r"(r2), "=r"(r3) : "r"(ad));
                b[nj*2][0] = r0;  b[nj*2][1] = r1;
                b[nj*2+1][0] = r2; b[nj*2+1][1] = r3;
            }
#pragma unroll
            for (int mi = 0; mi < 4; mi++)
#pragma unroll
                for (int ni = 0; ni < 4; ni++) {
                    asm volatile(
                        "mma.sync.aligned.m16n8k16.row.col.f32.f16.f16.f32 "
                        "{%0,%1,%2,%3}, {%4,%5,%6,%7}, {%8,%9}, {%0,%1,%2,%3};"
                        : "+f"(acc[mi][ni][0]), "+f"(acc[mi][ni][1]),
                          "+f"(acc[mi][ni][2]), "+f"(acc[mi][ni][3])
                        : "r"(a[mi][0]), "r"(a[mi][1]), "r"(a[mi][2]), "r"(a[mi][3]),
                          "r"(b[ni][0]), "r"(b[ni][1]));
                }
        }
        __syncthreads();
    }
}

#define EPI_ROW(wm, mi, r)  ((wm) + (mi)*16 + (lane >> 2) + (((r) >> 1) << 3))
#define EPI_COL(wn, ni, r)  ((wn) + (ni)*8 + ((lane & 3) << 1) + ((r) & 1))

// ---------------- phase 0: convert inputs to fp16 ----------------
__global__ void k_cvt(const float* __restrict__ X,  const float* __restrict__ Wq,
                      const float* __restrict__ Wk, const float* __restrict__ Wv,
                      const float* __restrict__ Wo)
{
    const int stride = gridDim.x * blockDim.x;
    const int i0 = blockIdx.x * blockDim.x + threadIdx.x;
    for (int i = i0; i < BB*SS*DD; i += stride) g_xh[i]  = __float2half_rn(X[i]);
    for (int i = i0; i < HH*DD*DD; i += stride) g_wqh[i] = __float2half_rn(Wq[i]);
    for (int i = i0; i < HH*DD*DD; i += stride) g_wkh[i] = __float2half_rn(Wk[i]);
    for (int i = i0; i < HH*DD*DD; i += stride) g_wvh[i] = __float2half_rn(Wv[i]);
    for (int i = i0; i < DD*HH*DD; i += stride) g_woh[i] = __float2half_rn(Wo[i]);
}

// ---------------- phase 1: QKV projections ----------------
// grid (64, 4, 24): z = proj*8 + h
__global__ void __launch_bounds__(256, 1) k_qkv(
    const float* __restrict__ bq, const float* __restrict__ bk,
    const float* __restrict__ bv)
{
    extern __shared__ __half sm[];
    const int m0 = blockIdx.x * 128, n0 = blockIdx.y * 128;
    const int z = blockIdx.z, proj = z >> 3, h = z & 7;

    const __half* Bmat = (proj == 0 ? g_wqh : proj == 1 ? g_wkh : g_wvh) + (size_t)h * DD * DD;
    float acc[4][4][4];
    gemm_h<8>(g_xh + (size_t)m0 * DD, Bmat + (size_t)n0 * DD, sm, acc);

    const int lane = threadIdx.x & 31, warp = threadIdx.x >> 5;
    const int wm = (warp & 1) * 64, wn = (warp >> 1) * 32;
    const float* bias = (proj == 0 ? bq : proj == 1 ? bk : bv) + h * DD;

    if (proj < 2) {
        __half* out = (proj == 0 ? g_qh : g_kh);
#pragma unroll
        for (int mi = 0; mi < 4; mi++)
#pragma unroll
            for (int ni = 0; ni < 4; ni++)
#pragma unroll
                for (int r = 0; r < 4; r++) {
                    int row = m0 + EPI_ROW(wm, mi, r);
                    int col = n0 + EPI_COL(wn, ni, r);
                    int b = row >> 10, s = row & 1023;
                    out[(((size_t)(b*HH + h)*SS + s) * DD) + col] =
                        __float2half_rn(acc[mi][ni][r] + bias[col]);
                }
    } else {
        // V: transpose through smem -> g_vth[b,h,e,s]
        __syncthreads();
        __half* T = sm;  // 128 x 136 halves
#pragma unroll
        for (int mi = 0; mi < 4; mi++)
#pragma unroll
            for (int ni = 0; ni < 4; ni++)
#pragma unroll
                for (int r = 0; r < 4; r++) {
                    int rl = EPI_ROW(wm, mi, r);
                    int cl = EPI_COL(wn, ni, r);
                    T[cl * 136 + rl] = __float2half_rn(acc[mi][ni][r] + bias[n0 + cl]);
                }
        __syncthreads();
        const int b  = m0 >> 10;
        const int s0 = m0 & 1023;
        __half* base = g_vth + (size_t)(b*HH + h) * DD * SS;
        for (int it = threadIdx.x; it < 128 * 64; it += 256) {
            int er  = it >> 6;            // e-row 0..127
            int cb2 = (it & 63) << 1;     // half2 start 0..126
            __half2 v = *(const __half2*)(T + er * 136 + cb2);
            *(__half2*)(base + (size_t)(n0 + er) * SS + s0 + cb2) = v;
        }
    }
}

// ---------------- phase 2: raw scores = Q K^T (unscaled; scale folded into softmax) ----------------
// grid (8, 8, 64)
__global__ void __launch_bounds__(256, 1) k_scores()
{
    extern __shared__ __half sm[];
    const int m0 = blockIdx.x * 128, n0 = blockIdx.y * 128, z = blockIdx.z;
    const __half* A = g_qh + (size_t)z * SS * DD + (size_t)m0 * DD;
    const __half* B = g_kh + (size_t)z * SS * DD + (size_t)n0 * DD;
    float acc[4][4][4];
    gemm_h<8>(A, B, sm, acc);

    __half* C = g_sch + (size_t)z * SS * SS;
    const int lane = threadIdx.x & 31, warp = threadIdx.x >> 5;
    const int wm = (warp & 1) * 64, wn = (warp >> 1) * 32;
#pragma unroll
    for (int mi = 0; mi < 4; mi++)
#pragma unroll
        for (int ni = 0; ni < 4; ni++)
#pragma unroll
            for (int r = 0; r < 4; r++) {
                int row = m0 + EPI_ROW(wm, mi, r);
                int col = n0 + EPI_COL(wn, ni, r);
                C[(size_t)row * SS + col] = __float2half_rn(acc[mi][ni][r]);
            }
}

// ---------------- phase 3: softmax (fp32 math, fp16 in/out) ----------------
// grid 8192 x 256: one warp per row
__global__ void k_softmax()
{
    const int row  = blockIdx.x * 8 + (threadIdx.x >> 5);
    const int lane = threadIdx.x & 31;
    __half2* p2 = (__half2*)(g_sch + (size_t)row * SS);
    const float scl = 1.0f / 262144.0f;   // 1/512^2

    float v[32];
#pragma unroll
    for (int i = 0; i < 16; i++) {
        float2 t = __half22float2(p2[lane + i * 32]);
        v[2*i]   = t.x * scl;
        v[2*i+1] = t.y * scl;
    }
    float m = v[0];
#pragma unroll
    for (int i = 1; i < 32; i++) m = fmaxf(m, v[i]);
#pragma unroll
    for (int o = 16; o > 0; o >>= 1) m = fmaxf(m, __shfl_xor_sync(0xffffffffu, m, o));
    float s = 0.f;
#pragma unroll
    for (int i = 0; i < 32; i++) { v[i] = __expf(v[i] - m); s += v[i]; }
#pragma unroll
    for (int o = 16; o > 0; o >>= 1) s += __shfl_xor_sync(0xffffffffu, s, o);
    float inv = 1.0f / s;
#pragma unroll
    for (int i = 0; i < 16; i++)
        p2[lane + i * 32] = __floats2half2_rn(v[2*i] * inv, v[2*i+1] * inv);
}

// ---------------- phase 4: H = P V -> hcat ----------------
// grid (8, 4, 64)
__global__ void __launch_bounds__(256, 1) k_pv()
{
    extern __shared__ __half sm[];
    const int m0 = blockIdx.x * 128, n0 = blockIdx.y * 128, z = blockIdx.z;
    const __half* A = g_sch + (size_t)z * SS * SS + (size_t)m0 * SS;  // P rows, K=1024
    const __half* B = g_vth + (size_t)z * DD * SS + (size_t)n0 * SS;  // V^T rows e
    float acc[4][4][4];
    gemm_h<16>(A, B, sm, acc);

    const int b = z >> 3, h = z & 7;
    const int lane = threadIdx.x & 31, warp = threadIdx.x >> 5;
    const int wm = (warp & 1) * 64, wn = (warp >> 1) * 32;
#pragma unroll
    for (int mi = 0; mi < 4; mi++)
#pragma unroll
        for (int ni = 0; ni < 4; ni++)
#pragma unroll
            for (int r = 0; r < 4; r++) {
                int s_ = m0 + EPI_ROW(wm, mi, r);
                int e  = n0 + EPI_COL(wn, ni, r);
                g_hh[((size_t)(b*SS + s_)) * (HH*DD) + h*DD + e] =
                    __float2half_rn(acc[mi][ni][r]);
            }
}

// ---------------- phase 5: out = Hcat Wo^T + bo ----------------
// grid (64, 4)
__global__ void __launch_bounds__(256, 1) k_out(const float* __restrict__ bo,
                                                float* __restrict__ out)
{
    extern __shared__ __half sm[];
    const int m0 = blockIdx.x * 128, n0 = blockIdx.y * 128;
    const __half* A = g_hh  + (size_t)m0 * (HH*DD);   // K = 4096
    const __half* B = g_woh + (size_t)n0 * (HH*DD);
    float acc[4][4][4];
    gemm_h<64>(A, B, sm, acc);

    const int lane = threadIdx.x & 31, warp = threadIdx.x >> 5;
    const int wm = (warp & 1) * 64, wn = (warp >> 1) * 32;
#pragma unroll
    for (int mi = 0; mi < 4; mi++)
#pragma unroll
        for (int ni = 0; ni < 4; ni++)
#pragma unroll
            for (int r = 0; r < 4; r++) {
                int row = m0 + EPI_ROW(wm, mi, r);
                int col = n0 + EPI_COL(wn, ni, r);
                out[(size_t)row * DD + col] = acc[mi][ni][r] + bo[col];
            }
}

// ---------------- host launcher ----------------
extern "C" void kernel_launch(void* const* d_in, const int* in_sizes, int n_in,
                              void* d_out, int out_size)
{
    const float* X  = (const float*)d_in[0];
    const float* Wq = (const float*)d_in[1];
    const float* bq = (const float*)d_in[2];
    const float* Wk = (const float*)d_in[3];
    const float* bk = (const float*)d_in[4];
    const float* Wv = (const float*)d_in[5];
    const float* bv = (const float*)d_in[6];
    const float* Wo = (const float*)d_in[7];
    const float* bo = (const float*)d_in[8];
    float* out = (float*)d_out;

    const int SMEM = 65536;   // 2 stages x 32KB
    cudaFuncSetAttribute(k_qkv,    cudaFuncAttributeMaxDynamicSharedMemorySize, SMEM);
    cudaFuncSetAttribute(k_scores, cudaFuncAttributeMaxDynamicSharedMemorySize, SMEM);
    cudaFuncSetAttribute(k_pv,     cudaFuncAttributeMaxDynamicSharedMemorySize, SMEM);
    cudaFuncSetAttribute(k_out,    cudaFuncAttributeMaxDynamicSharedMemorySize, SMEM);

    k_cvt<<<2048, 256>>>(X, Wq, Wk, Wv, Wo);
    k_qkv<<<dim3(64, 4, 24), 256, SMEM>>>(bq, bk, bv);
    k_scores<<<dim3(8, 8, 64), 256, SMEM>>>();
    k_softmax<<<8192, 256>>>();
    k_pv<<<dim3(8, 4, 64), 256, SMEM>>>();
    k_out<<<dim3(64, 4), 256, SMEM>>>(bo, out);
}

// round 10
// speedup vs baseline: 2.0400x; 1.2160x over previous
#include <cuda_runtime.h>
#include <cuda_fp16.h>
#include <cstdint>

#define BB 8
#define SS 1024
#define DD 512
#define HH 8

#define STG_H (128*64*2)     // halves per stage (A 128x64 + B 128x64)

// ---------------- fp16 staged tensors ----------------
__device__ __align__(256) __half g_xh [BB*SS*DD];
__device__ __align__(256) __half g_wqh[HH*DD*DD];
__device__ __align__(256) __half g_wkh[HH*DD*DD];
__device__ __align__(256) __half g_wvh[HH*DD*DD];
__device__ __align__(256) __half g_woh[DD*HH*DD];
__device__ __align__(256) __half g_qh [BB*HH*SS*DD];        // [B,H,S,E]
__device__ __align__(256) __half g_kh [BB*HH*SS*DD];        // [B,H,S,E]
__device__ __align__(256) __half g_vth[BB*HH*DD*SS];        // [B,H,E,S]
__device__ __align__(256) __half g_sch[(size_t)BB*HH*SS*SS];// [B,H,S,S]
__device__ __align__(256) __half g_hh [BB*SS*HH*DD];        // [B,S,H*E]

// ---------------- helpers ----------------
__device__ __forceinline__ unsigned smem_u32(const void* p) {
    return (unsigned)__cvta_generic_to_shared(p);
}
__device__ __forceinline__ void cp16(void* dst, const void* src) {
    asm volatile("cp.async.cg.shared.global [%0], [%1], 16;\n"
                 :: "r"(smem_u32(dst)), "l"(src));
}

// ---------------- fp16 GEMM mainloop: 3-stage cp.async, 1 sync/iter ----------------
// C[128,128] += A[128,K] * B[128,K]^T, fp16 operands, fp32 accumulate.
// K-tile = 64 halves (128B rows, XOR-swizzled). smem: 3 stages x 32KB.
template<int KT>   // KT = K/64, KT >= 2
__device__ __forceinline__ void gemm_h(const __half* __restrict__ Ag,
                                       const __half* __restrict__ Bg,
                                       __half* sm, float (&acc)[4][4][4])
{
    const int K = KT * 64;
    const int tid  = threadIdx.x;
    const int lane = tid & 31;
    const int warp = tid >> 5;
    const int wm = (warp & 1) * 64;   // 2 warps along M
    const int wn = (warp >> 1) * 32;  // 4 warps along N

#pragma unroll
    for (int mi = 0; mi < 4; mi++)
#pragma unroll
        for (int ni = 0; ni < 4; ni++)
#pragma unroll
            for (int r = 0; r < 4; r++) acc[mi][ni][r] = 0.f;

    const int srow = tid >> 3;   // 0..31
    const int sch  = tid & 7;    // 16B chunk within 128B row

    auto stage = [&](int s, int kt) {
        __half* sA = sm + s * STG_H;
        __half* sB = sA + 128 * 64;
        const __half* ap = Ag + (size_t)srow * K + kt * 64 + sch * 8;
        const __half* bp = Bg + (size_t)srow * K + kt * 64 + sch * 8;
#pragma unroll
        for (int i = 0; i < 4; i++) {
            int r = srow + i * 32;
            int sw = (sch ^ (r & 7)) * 8;         // halves
            cp16(sA + r * 64 + sw, ap + (size_t)i * 32 * K);
            cp16(sB + r * 64 + sw, bp + (size_t)i * 32 * K);
        }
        asm volatile("cp.async.commit_group;\n");
    };

    stage(0, 0);
    stage(1, 1);

#pragma unroll 1
    for (int kt = 0; kt < KT; kt++) {
        if (kt < KT - 1) asm volatile("cp.async.wait_group 1;\n");
        else             asm volatile("cp.async.wait_group 0;\n");
        __syncthreads();

        if (kt + 2 < KT) stage((kt + 2) % 3, kt + 2);

        const __half* sA = sm + (kt % 3) * STG_H;
        const __half* sB = sA + 128 * 64;

#pragma unroll
        for (int ks = 0; ks < 4; ks++) {          // 4 x k16 per 64-tile
            uint32_t a[4][4];
#pragma unroll
            for (int mi = 0; mi < 4; mi++) {
                int r  = wm + mi * 16 + (lane & 15);
                int ch = 2 * ks + (lane >> 4);
                unsigned ad = smem_u32(sA + r * 64 + ((ch ^ (r & 7)) * 8));
                asm volatile("ldmatrix.sync.aligned.m8n8.x4.shared.b16 {%0,%1,%2,%3}, [%4];"
                             : "=r"(a[mi][0]), "=r"(a[mi][1]), "=r"(a[mi][2]), "=r"(a[mi][3])
                             : "r"(ad));
            }
            uint32_t b[4][2];
#pragma unroll
            for (int nj = 0; nj < 2; nj++) {
                int nr = wn + nj * 16 + ((lane >> 4) << 3) + (lane & 7);
                int ch = 2 * ks + ((lane >> 3) & 1);
                unsigned ad = smem_u32(sB + nr * 64 + ((ch ^ (nr & 7)) * 8));
                uint32_t r0, r1, r2, r3;
                asm volatile("ldmatrix.sync.aligned.m8n8.x4.shared.b16 {%0,%1,%2,%3}, [%4];"
                             : "=r"(r0), "=r"(r1), "=r"(r2), "=r"(r3) : "r"(ad));
                b[nj*2][0] = r0;  b[nj*2][1] = r1;
                b[nj*2+1][0] = r2; b[nj*2+1][1] = r3;
            }
#pragma unroll
            for (int mi = 0; mi < 4; mi++)
#pragma unroll
                for (int ni = 0; ni < 4; ni++) {
                    asm volatile(
                        "mma.sync.aligned.m16n8k16.row.col.f32.f16.f16.f32 "
                        "{%0,%1,%2,%3}, {%4,%5,%6,%7}, {%8,%9}, {%0,%1,%2,%3};"
                        : "+f"(acc[mi][ni][0]), "+f"(acc[mi][ni][1]),
                          "+f"(acc[mi][ni][2]), "+f"(acc[mi][ni][3])
                        : "r"(a[mi][0]), "r"(a[mi][1]), "r"(a[mi][2]), "r"(a[mi][3]),
                          "r"(b[ni][0]), "r"(b[ni][1]));
                }
        }
        __syncthreads();  // re-used only when kt%3 buffer rewritten; keep WAR-safe for stage issue next iter
    }
}

#define EPI_ROW(wm, mi, r)  ((wm) + (mi)*16 + (lane >> 2) + (((r) >> 1) << 3))
#define EPI_COL(wn, ni, r)  ((wn) + (ni)*8 + ((lane & 3) << 1) + ((r) & 1))

// ---------------- phase 0: convert inputs to fp16 ----------------
__global__ void k_cvt(const float* __restrict__ X,  const float* __restrict__ Wq,
                      const float* __restrict__ Wk, const float* __restrict__ Wv,
                      const float* __restrict__ Wo)
{
    const int stride = gridDim.x * blockDim.x;
    const int i0 = blockIdx.x * blockDim.x + threadIdx.x;
    for (int i = i0; i < BB*SS*DD; i += stride) g_xh[i]  = __float2half_rn(X[i]);
    for (int i = i0; i < HH*DD*DD; i += stride) g_wqh[i] = __float2half_rn(Wq[i]);
    for (int i = i0; i < HH*DD*DD; i += stride) g_wkh[i] = __float2half_rn(Wk[i]);
    for (int i = i0; i < HH*DD*DD; i += stride) g_wvh[i] = __float2half_rn(Wv[i]);
    for (int i = i0; i < DD*HH*DD; i += stride) g_woh[i] = __float2half_rn(Wo[i]);
}

// ---------------- phase 1: QKV projections ----------------
// grid (64, 4, 24): z = proj*8 + h
__global__ void __launch_bounds__(256, 2) k_qkv(
    const float* __restrict__ bq, const float* __restrict__ bk,
    const float* __restrict__ bv)
{
    extern __shared__ __half sm[];
    const int m0 = blockIdx.x * 128, n0 = blockIdx.y * 128;
    const int z = blockIdx.z, proj = z >> 3, h = z & 7;

    const __half* Bmat = (proj == 0 ? g_wqh : proj == 1 ? g_wkh : g_wvh) + (size_t)h * DD * DD;
    float acc[4][4][4];
    gemm_h<8>(g_xh + (size_t)m0 * DD, Bmat + (size_t)n0 * DD, sm, acc);

    const int lane = threadIdx.x & 31, warp = threadIdx.x >> 5;
    const int wm = (warp & 1) * 64, wn = (warp >> 1) * 32;
    const float* bias = (proj == 0 ? bq : proj == 1 ? bk : bv) + h * DD;

    if (proj < 2) {
        __half* out = (proj == 0 ? g_qh : g_kh);
#pragma unroll
        for (int mi = 0; mi < 4; mi++)
#pragma unroll
            for (int ni = 0; ni < 4; ni++)
#pragma unroll
                for (int r = 0; r < 4; r++) {
                    int row = m0 + EPI_ROW(wm, mi, r);
                    int col = n0 + EPI_COL(wn, ni, r);
                    int b = row >> 10, s = row & 1023;
                    out[(((size_t)(b*HH + h)*SS + s) * DD) + col] =
                        __float2half_rn(acc[mi][ni][r] + bias[col]);
                }
    } else {
        // V: transpose through smem -> g_vth[b,h,e,s]
        __syncthreads();
        __half* T = sm;  // 128 x 136 halves
#pragma unroll
        for (int mi = 0; mi < 4; mi++)
#pragma unroll
            for (int ni = 0; ni < 4; ni++)
#pragma unroll
                for (int r = 0; r < 4; r++) {
                    int rl = EPI_ROW(wm, mi, r);
                    int cl = EPI_COL(wn, ni, r);
                    T[cl * 136 + rl] = __float2half_rn(acc[mi][ni][r] + bias[n0 + cl]);
                }
        __syncthreads();
        const int b  = m0 >> 10;
        const int s0 = m0 & 1023;
        __half* base = g_vth + (size_t)(b*HH + h) * DD * SS;
        for (int it = threadIdx.x; it < 128 * 64; it += 256) {
            int er  = it >> 6;            // e-row 0..127
            int cb2 = (it & 63) << 1;     // half2 start 0..126
            __half2 v = *(const __half2*)(T + er * 136 + cb2);
            *(__half2*)(base + (size_t)(n0 + er) * SS + s0 + cb2) = v;
        }
    }
}

// ---------------- phase 2: raw scores = Q K^T (scale folded into softmax) ----------------
// grid (8, 8, 64)
__global__ void __launch_bounds__(256, 2) k_scores()
{
    extern __shared__ __half sm[];
    const int m0 = blockIdx.x * 128, n0 = blockIdx.y * 128, z = blockIdx.z;
    const __half* A = g_qh + (size_t)z * SS * DD + (size_t)m0 * DD;
    const __half* B = g_kh + (size_t)z * SS * DD + (size_t)n0 * DD;
    float acc[4][4][4];
    gemm_h<8>(A, B, sm, acc);

    __half* C = g_sch + (size_t)z * SS * SS;
    const int lane = threadIdx.x & 31, warp = threadIdx.x >> 5;
    const int wm = (warp & 1) * 64, wn = (warp >> 1) * 32;
#pragma unroll
    for (int mi = 0; mi < 4; mi++)
#pragma unroll
        for (int ni = 0; ni < 4; ni++)
#pragma unroll
            for (int r = 0; r < 4; r++) {
                int row = m0 + EPI_ROW(wm, mi, r);
                int col = n0 + EPI_COL(wn, ni, r);
                C[(size_t)row * SS + col] = __float2half_rn(acc[mi][ni][r]);
            }
}

// ---------------- phase 3: softmax (fp32 math, fp16 in/out) ----------------
__global__ void k_softmax()
{
    const int row  = blockIdx.x * 8 + (threadIdx.x >> 5);
    const int lane = threadIdx.x & 31;
    __half2* p2 = (__half2*)(g_sch + (size_t)row * SS);
    const float scl = 1.0f / 262144.0f;   // 1/512^2

    float v[32];
#pragma unroll
    for (int i = 0; i < 16; i++) {
        float2 t = __half22float2(p2[lane + i * 32]);
        v[2*i]   = t.x * scl;
        v[2*i+1] = t.y * scl;
    }
    float m = v[0];
#pragma unroll
    for (int i = 1; i < 32; i++) m = fmaxf(m, v[i]);
#pragma unroll
    for (int o = 16; o > 0; o >>= 1) m = fmaxf(m, __shfl_xor_sync(0xffffffffu, m, o));
    float s = 0.f;
#pragma unroll
    for (int i = 0; i < 32; i++) { v[i] = __expf(v[i] - m); s += v[i]; }
#pragma unroll
    for (int o = 16; o > 0; o >>= 1) s += __shfl_xor_sync(0xffffffffu, s, o);
    float inv = 1.0f / s;
#pragma unroll
    for (int i = 0; i < 16; i++)
        p2[lane + i * 32] = __floats2half2_rn(v[2*i] * inv, v[2*i+1] * inv);
}

// ---------------- phase 4: H = P V -> hcat ----------------
// grid (8, 4, 64)
__global__ void __launch_bounds__(256, 2) k_pv()
{
    extern __shared__ __half sm[];
    const int m0 = blockIdx.x * 128, n0 = blockIdx.y * 128, z = blockIdx.z;
    const __half* A = g_sch + (size_t)z * SS * SS + (size_t)m0 * SS;  // P rows, K=1024
    const __half* B = g_vth + (size_t)z * DD * SS + (size_t)n0 * SS;  // V^T rows e
    float acc[4][4][4];
    gemm_h<16>(A, B, sm, acc);

    const int b = z >> 3, h = z & 7;
    const int lane = threadIdx.x & 31, warp = threadIdx.x >> 5;
    const int wm = (warp & 1) * 64, wn = (warp >> 1) * 32;
#pragma unroll
    for (int mi = 0; mi < 4; mi++)
#pragma unroll
        for (int ni = 0; ni < 4; ni++)
#pragma unroll
            for (int r = 0; r < 4; r++) {
                int s_ = m0 + EPI_ROW(wm, mi, r);
                int e  = n0 + EPI_COL(wn, ni, r);
                g_hh[((size_t)(b*SS + s_)) * (HH*DD) + h*DD + e] =
                    __float2half_rn(acc[mi][ni][r]);
            }
}

// ---------------- phase 5: out = Hcat Wo^T + bo ----------------
// grid (64, 4)
__global__ void __launch_bounds__(256, 2) k_out(const float* __restrict__ bo,
                                                float* __restrict__ out)
{
    extern __shared__ __half sm[];
    const int m0 = blockIdx.x * 128, n0 = blockIdx.y * 128;
    const __half* A = g_hh  + (size_t)m0 * (HH*DD);   // K = 4096
    const __half* B = g_woh + (size_t)n0 * (HH*DD);
    float acc[4][4][4];
    gemm_h<64>(A, B, sm, acc);

    const int lane = threadIdx.x & 31, warp = threadIdx.x >> 5;
    const int wm = (warp & 1) * 64, wn = (warp >> 1) * 32;
#pragma unroll
    for (int mi = 0; mi < 4; mi++)
#pragma unroll
        for (int ni = 0; ni < 4; ni++)
#pragma unroll
            for (int r = 0; r < 4; r++) {
                int row = m0 + EPI_ROW(wm, mi, r);
                int col = n0 + EPI_COL(wn, ni, r);
                out[(size_t)row * DD + col] = acc[mi][ni][r] + bo[col];
            }
}

// ---------------- host launcher ----------------
extern "C" void kernel_launch(void* const* d_in, const int* in_sizes, int n_in,
                              void* d_out, int out_size)
{
    const float* X  = (const float*)d_in[0];
    const float* Wq = (const float*)d_in[1];
    const float* bq = (const float*)d_in[2];
    const float* Wk = (const float*)d_in[3];
    const float* bk = (const float*)d_in[4];
    const float* Wv = (const float*)d_in[5];
    const float* bv = (const float*)d_in[6];
    const float* Wo = (const float*)d_in[7];
    const float* bo = (const float*)d_in[8];
    float* out = (float*)d_out;

    const int SMEM = 3 * STG_H * 2;   // 98304 bytes: 3 stages x 32KB
    cudaFuncSetAttribute(k_qkv,    cudaFuncAttributeMaxDynamicSharedMemorySize, SMEM);
    cudaFuncSetAttribute(k_scores, cudaFuncAttributeMaxDynamicSharedMemorySize, SMEM);
    cudaFuncSetAttribute(k_pv,     cudaFuncAttributeMaxDynamicSharedMemorySize, SMEM);
    cudaFuncSetAttribute(k_out,    cudaFuncAttributeMaxDynamicSharedMemorySize, SMEM);

    k_cvt<<<2048, 256>>>(X, Wq, Wk, Wv, Wo);
    k_qkv<<<dim3(64, 4, 24), 256, SMEM>>>(bq, bk, bv);
    k_scores<<<dim3(8, 8, 64), 256, SMEM>>>();
    k_softmax<<<8192, 256>>>();
    k_pv<<<dim3(8, 4, 64), 256, SMEM>>>();
    k_out<<<dim3(64, 4), 256, SMEM>>>(bo, out);
}

// round 11
// speedup vs baseline: 2.1448x; 1.0514x over previous
#include <cuda_runtime.h>
#include <cuda_fp16.h>
#include <cstdint>

#define BB 8
#define SS 1024
#define DD 512
#define HH 8

#define STG_H (128*64*2)     // halves per stage (A 128x64 + B 128x64)

// ---------------- fp16 staged tensors ----------------
__device__ __align__(256) __half g_xh [BB*SS*DD];
__device__ __align__(256) __half g_wqh[HH*DD*DD];
__device__ __align__(256) __half g_wkh[HH*DD*DD];
__device__ __align__(256) __half g_wvh[HH*DD*DD];
__device__ __align__(256) __half g_woh[DD*HH*DD];
__device__ __align__(256) __half g_qh [BB*HH*SS*DD];        // [B,H,S,E]
__device__ __align__(256) __half g_kh [BB*HH*SS*DD];        // [B,H,S,E]
__device__ __align__(256) __half g_vth[BB*HH*DD*SS];        // [B,H,E,S]
__device__ __align__(256) __half g_sch[(size_t)BB*HH*SS*SS];// [B,H,S,S]
__device__ __align__(256) __half g_hh [BB*SS*HH*DD];        // [B,S,H*E]

// ---------------- helpers ----------------
__device__ __forceinline__ unsigned smem_u32(const void* p) {
    return (unsigned)__cvta_generic_to_shared(p);
}
__device__ __forceinline__ void cp16(void* dst, const void* src) {
    asm volatile("cp.async.cg.shared.global [%0], [%1], 16;\n"
                 :: "r"(smem_u32(dst)), "l"(src));
}

// ---------------- fp16 GEMM mainloop: 4 warps, 64x64 warp tiles ----------------
// C[128,128] += A[128,K] * B[128,K]^T, fp16 operands, fp32 accumulate.
// 128 threads as 2x2 warps of 64x64. 3-stage cp.async, 1 sync per k-iter.
template<int KT>   // KT = K/64, KT >= 2
__device__ __forceinline__ void gemm_h(const __half* __restrict__ Ag,
                                       const __half* __restrict__ Bg,
                                       __half* sm, float (&acc)[4][8][4])
{
    const int K = KT * 64;
    const int tid  = threadIdx.x;
    const int lane = tid & 31;
    const int warp = tid >> 5;
    const int wm = (warp & 1) * 64;   // 2 warps along M
    const int wn = (warp >> 1) * 64;  // 2 warps along N

#pragma unroll
    for (int mi = 0; mi < 4; mi++)
#pragma unroll
        for (int ni = 0; ni < 8; ni++)
#pragma unroll
            for (int r = 0; r < 4; r++) acc[mi][ni][r] = 0.f;

    const int srow = tid >> 3;   // 0..15
    const int sch  = tid & 7;    // 16B chunk within 128B row

    auto stage = [&](int s, int kt) {
        __half* sA = sm + s * STG_H;
        __half* sB = sA + 128 * 64;
        const __half* ap = Ag + (size_t)srow * K + kt * 64 + sch * 8;
        const __half* bp = Bg + (size_t)srow * K + kt * 64 + sch * 8;
#pragma unroll
        for (int i = 0; i < 8; i++) {
            int r = srow + i * 16;
            int sw = (sch ^ (r & 7)) * 8;         // halves
            cp16(sA + r * 64 + sw, ap + (size_t)i * 16 * K);
            cp16(sB + r * 64 + sw, bp + (size_t)i * 16 * K);
        }
        asm volatile("cp.async.commit_group;\n");
    };

    stage(0, 0);
    stage(1, 1);

#pragma unroll 1
    for (int kt = 0; kt < KT; kt++) {
        if (kt < KT - 1) asm volatile("cp.async.wait_group 1;\n");
        else             asm volatile("cp.async.wait_group 0;\n");
        __syncthreads();

        if (kt + 2 < KT) stage((kt + 2) % 3, kt + 2);

        const __half* sA = sm + (kt % 3) * STG_H;
        const __half* sB = sA + 128 * 64;

#pragma unroll
        for (int ks = 0; ks < 4; ks++) {          // 4 x k16 per 64-tile
            uint32_t a[4][4];
#pragma unroll
            for (int mi = 0; mi < 4; mi++) {
                int r  = wm + mi * 16 + (lane & 15);
                int ch = 2 * ks + (lane >> 4);
                unsigned ad = smem_u32(sA + r * 64 + ((ch ^ (r & 7)) * 8));
                asm volatile("ldmatrix.sync.aligned.m8n8.x4.shared.b16 {%0,%1,%2,%3}, [%4];"
                             : "=r"(a[mi][0]), "=r"(a[mi][1]), "=r"(a[mi][2]), "=r"(a[mi][3])
                             : "r"(ad));
            }
            uint32_t b[8][2];
#pragma unroll
            for (int nj = 0; nj < 4; nj++) {
                int nr = wn + nj * 16 + ((lane >> 4) << 3) + (lane & 7);
                int ch = 2 * ks + ((lane >> 3) & 1);
                unsigned ad = smem_u32(sB + nr * 64 + ((ch ^ (nr & 7)) * 8));
                uint32_t r0, r1, r2, r3;
                asm volatile("ldmatrix.sync.aligned.m8n8.x4.shared.b16 {%0,%1,%2,%3}, [%4];"
                             : "=r"(r0), "=r"(r1), "=r"(r2), "=r"(r3) : "r"(ad));
                b[nj*2][0] = r0;  b[nj*2][1] = r1;
                b[nj*2+1][0] = r2; b[nj*2+1][1] = r3;
            }
#pragma unroll
            for (int mi = 0; mi < 4; mi++)
#pragma unroll
                for (int ni = 0; ni < 8; ni++) {
                    asm volatile(
                        "mma.sync.aligned.m16n8k16.row.col.f32.f16.f16.f32 "
                        "{%0,%1,%2,%3}, {%4,%5,%6,%7}, {%8,%9}, {%0,%1,%2,%3};"
                        : "+f"(acc[mi][ni][0]), "+f"(acc[mi][ni][1]),
                          "+f"(acc[mi][ni][2]), "+f"(acc[mi][ni][3])
                        : "r"(a[mi][0]), "r"(a[mi][1]), "r"(a[mi][2]), "r"(a[mi][3]),
                          "r"(b[ni][0]), "r"(b[ni][1]));
                }
        }
        __syncthreads();
    }
}

#define EPI_ROW(wm, mi, r)  ((wm) + (mi)*16 + (lane >> 2) + (((r) >> 1) << 3))
#define EPI_COL(wn, ni, r)  ((wn) + (ni)*8 + ((lane & 3) << 1) + ((r) & 1))

// ---------------- phase 0: convert inputs to fp16 ----------------
__global__ void k_cvt(const float* __restrict__ X,  const float* __restrict__ Wq,
                      const float* __restrict__ Wk, const float* __restrict__ Wv,
                      const float* __restrict__ Wo)
{
    const int stride = gridDim.x * blockDim.x;
    const int i0 = blockIdx.x * blockDim.x + threadIdx.x;
    for (int i = i0; i < BB*SS*DD; i += stride) g_xh[i]  = __float2half_rn(X[i]);
    for (int i = i0; i < HH*DD*DD; i += stride) g_wqh[i] = __float2half_rn(Wq[i]);
    for (int i = i0; i < HH*DD*DD; i += stride) g_wkh[i] = __float2half_rn(Wk[i]);
    for (int i = i0; i < HH*DD*DD; i += stride) g_wvh[i] = __float2half_rn(Wv[i]);
    for (int i = i0; i < DD*HH*DD; i += stride) g_woh[i] = __float2half_rn(Wo[i]);
}

// ---------------- phase 1: QKV projections ----------------
// grid (64, 4, 24): z = proj*8 + h
__global__ void __launch_bounds__(128, 2) k_qkv(
    const float* __restrict__ bq, const float* __restrict__ bk,
    const float* __restrict__ bv)
{
    extern __shared__ __half sm[];
    const int m0 = blockIdx.x * 128, n0 = blockIdx.y * 128;
    const int z = blockIdx.z, proj = z >> 3, h = z & 7;

    const __half* Bmat = (proj == 0 ? g_wqh : proj == 1 ? g_wkh : g_wvh) + (size_t)h * DD * DD;
    float acc[4][8][4];
    gemm_h<8>(g_xh + (size_t)m0 * DD, Bmat + (size_t)n0 * DD, sm, acc);

    const int lane = threadIdx.x & 31, warp = threadIdx.x >> 5;
    const int wm = (warp & 1) * 64, wn = (warp >> 1) * 64;
    const float* bias = (proj == 0 ? bq : proj == 1 ? bk : bv) + h * DD;

    if (proj < 2) {
        __half* out = (proj == 0 ? g_qh : g_kh);
#pragma unroll
        for (int mi = 0; mi < 4; mi++)
#pragma unroll
            for (int ni = 0; ni < 8; ni++)
#pragma unroll
                for (int r = 0; r < 4; r++) {
                    int row = m0 + EPI_ROW(wm, mi, r);
                    int col = n0 + EPI_COL(wn, ni, r);
                    int b = row >> 10, s = row & 1023;
                    out[(((size_t)(b*HH + h)*SS + s) * DD) + col] =
                        __float2half_rn(acc[mi][ni][r] + bias[col]);
                }
    } else {
        // V: transpose through smem -> g_vth[b,h,e,s]
        __syncthreads();
        __half* T = sm;  // 128 x 136 halves
#pragma unroll
        for (int mi = 0; mi < 4; mi++)
#pragma unroll
            for (int ni = 0; ni < 8; ni++)
#pragma unroll
                for (int r = 0; r < 4; r++) {
                    int rl = EPI_ROW(wm, mi, r);
                    int cl = EPI_COL(wn, ni, r);
                    T[cl * 136 + rl] = __float2half_rn(acc[mi][ni][r] + bias[n0 + cl]);
                }
        __syncthreads();
        const int b  = m0 >> 10;
        const int s0 = m0 & 1023;
        __half* base = g_vth + (size_t)(b*HH + h) * DD * SS;
        for (int it = threadIdx.x; it < 128 * 64; it += 128) {
            int er  = it >> 6;            // e-row 0..127
            int cb2 = (it & 63) << 1;     // half2 start 0..126
            __half2 v = *(const __half2*)(T + er * 136 + cb2);
            *(__half2*)(base + (size_t)(n0 + er) * SS + s0 + cb2) = v;
        }
    }
}

// ---------------- phase 2: raw scores = Q K^T (scale folded into softmax) ----------------
// grid (8, 8, 64)
__global__ void __launch_bounds__(128, 2) k_scores()
{
    extern __shared__ __half sm[];
    const int m0 = blockIdx.x * 128, n0 = blockIdx.y * 128, z = blockIdx.z;
    const __half* A = g_qh + (size_t)z * SS * DD + (size_t)m0 * DD;
    const __half* B = g_kh + (size_t)z * SS * DD + (size_t)n0 * DD;
    float acc[4][8][4];
    gemm_h<8>(A, B, sm, acc);

    __half* C = g_sch + (size_t)z * SS * SS;
    const int lane = threadIdx.x & 31, warp = threadIdx.x >> 5;
    const int wm = (warp & 1) * 64, wn = (warp >> 1) * 64;
#pragma unroll
    for (int mi = 0; mi < 4; mi++)
#pragma unroll
        for (int ni = 0; ni < 8; ni++)
#pragma unroll
            for (int r = 0; r < 4; r++) {
                int row = m0 + EPI_ROW(wm, mi, r);
                int col = n0 + EPI_COL(wn, ni, r);
                C[(size_t)row * SS + col] = __float2half_rn(acc[mi][ni][r]);
            }
}

// ---------------- phase 3: softmax (fp32 math, fp16 in/out) ----------------
__global__ void k_softmax()
{
    const int row  = blockIdx.x * 8 + (threadIdx.x >> 5);
    const int lane = threadIdx.x & 31;
    __half2* p2 = (__half2*)(g_sch + (size_t)row * SS);
    const float scl = 1.0f / 262144.0f;   // 1/512^2

    float v[32];
#pragma unroll
    for (int i = 0; i < 16; i++) {
        float2 t = __half22float2(p2[lane + i * 32]);
        v[2*i]   = t.x * scl;
        v[2*i+1] = t.y * scl;
    }
    float m = v[0];
#pragma unroll
    for (int i = 1; i < 32; i++) m = fmaxf(m, v[i]);
#pragma unroll
    for (int o = 16; o > 0; o >>= 1) m = fmaxf(m, __shfl_xor_sync(0xffffffffu, m, o));
    float s = 0.f;
#pragma unroll
    for (int i = 0; i < 32; i++) { v[i] = __expf(v[i] - m); s += v[i]; }
#pragma unroll
    for (int o = 16; o > 0; o >>= 1) s += __shfl_xor_sync(0xffffffffu, s, o);
    float inv = 1.0f / s;
#pragma unroll
    for (int i = 0; i < 16; i++)
        p2[lane + i * 32] = __floats2half2_rn(v[2*i] * inv, v[2*i+1] * inv);
}

// ---------------- phase 4: H = P V -> hcat ----------------
// grid (8, 4, 64)
__global__ void __launch_bounds__(128, 2) k_pv()
{
    extern __shared__ __half sm[];
    const int m0 = blockIdx.x * 128, n0 = blockIdx.y * 128, z = blockIdx.z;
    const __half* A = g_sch + (size_t)z * SS * SS + (size_t)m0 * SS;  // P rows, K=1024
    const __half* B = g_vth + (size_t)z * DD * SS + (size_t)n0 * SS;  // V^T rows e
    float acc[4][8][4];
    gemm_h<16>(A, B, sm, acc);

    const int b = z >> 3, h = z & 7;
    const int lane = threadIdx.x & 31, warp = threadIdx.x >> 5;
    const int wm = (warp & 1) * 64, wn = (warp >> 1) * 64;
#pragma unroll
    for (int mi = 0; mi < 4; mi++)
#pragma unroll
        for (int ni = 0; ni < 8; ni++)
#pragma unroll
            for (int r = 0; r < 4; r++) {
                int s_ = m0 + EPI_ROW(wm, mi, r);
                int e  = n0 + EPI_COL(wn, ni, r);
                g_hh[((size_t)(b*SS + s_)) * (HH*DD) + h*DD + e] =
                    __float2half_rn(acc[mi][ni][r]);
            }
}

// ---------------- phase 5: out = Hcat Wo^T + bo ----------------
// grid (64, 4)
__global__ void __launch_bounds__(128, 2) k_out(const float* __restrict__ bo,
                                                float* __restrict__ out)
{
    extern __shared__ __half sm[];
    const int m0 = blockIdx.x * 128, n0 = blockIdx.y * 128;
    const __half* A = g_hh  + (size_t)m0 * (HH*DD);   // K = 4096
    const __half* B = g_woh + (size_t)n0 * (HH*DD);
    float acc[4][8][4];
    gemm_h<64>(A, B, sm, acc);

    const int lane = threadIdx.x & 31, warp = threadIdx.x >> 5;
    const int wm = (warp & 1) * 64, wn = (warp >> 1) * 64;
#pragma unroll
    for (int mi = 0; mi < 4; mi++)
#pragma unroll
        for (int ni = 0; ni < 8; ni++)
#pragma unroll
            for (int r = 0; r < 4; r++) {
                int row = m0 + EPI_ROW(wm, mi, r);
                int col = n0 + EPI_COL(wn, ni, r);
                out[(size_t)row * DD + col] = acc[mi][ni][r] + bo[col];
            }
}

// ---------------- host launcher ----------------
extern "C" void kernel_launch(void* const* d_in, const int* in_sizes, int n_in,
                              void* d_out, int out_size)
{
    const float* X  = (const float*)d_in[0];
    const float* Wq = (const float*)d_in[1];
    const float* bq = (const float*)d_in[2];
    const float* Wk = (const float*)d_in[3];
    const float* bk = (const float*)d_in[4];
    const float* Wv = (const float*)d_in[5];
    const float* bv = (const float*)d_in[6];
    const float* Wo = (const float*)d_in[7];
    const float* bo = (const float*)d_in[8];
    float* out = (float*)d_out;

    const int SMEM = 3 * STG_H * 2;   // 98304 bytes: 3 stages x 32KB
    cudaFuncSetAttribute(k_qkv,    cudaFuncAttributeMaxDynamicSharedMemorySize, SMEM);
    cudaFuncSetAttribute(k_scores, cudaFuncAttributeMaxDynamicSharedMemorySize, SMEM);
    cudaFuncSetAttribute(k_pv,     cudaFuncAttributeMaxDynamicSharedMemorySize, SMEM);
    cudaFuncSetAttribute(k_out,    cudaFuncAttributeMaxDynamicSharedMemorySize, SMEM);

    k_cvt<<<2048, 256>>>(X, Wq, Wk, Wv, Wo);
    k_qkv<<<dim3(64, 4, 24), 128, SMEM>>>(bq, bk, bv);
    k_scores<<<dim3(8, 8, 64), 128, SMEM>>>();
    k_softmax<<<8192, 256>>>();
    k_pv<<<dim3(8, 4, 64), 128, SMEM>>>();
    k_out<<<dim3(64, 4), 128, SMEM>>>(bo, out);
}

// round 12
// speedup vs baseline: 2.4418x; 1.1384x over previous
#include <cuda_runtime.h>
#include <cuda_fp16.h>
#include <cstdint>

#define BB 8
#define SS 1024
#define DD 512
#define HH 8

#define STG_H (128*64*2)     // halves per stage (A 128x64 + B 128x64)

// ---------------- fp16 staged tensors ----------------
__device__ __align__(256) __half g_xh [BB*SS*DD];           // X [B,S,D]
__device__ __align__(256) __half g_xt [BB*DD*SS];           // X^T [B,D,S]
__device__ __align__(256) __half g_wqh[HH*DD*DD];
__device__ __align__(256) __half g_wkh[HH*DD*DD];
__device__ __align__(256) __half g_wvh[HH*DD*DD];
__device__ __align__(256) __half g_woh[DD*HH*DD];           // Wo [512,4096]
__device__ __align__(256) __half g_wqt[HH*DD*DD];           // Wq^T per head [i][e]
__device__ __align__(256) __half g_wkt[HH*DD*DD];
__device__ __align__(256) __half g_wvt[HH*DD*DD];
__device__ __align__(256) __half g_mh [HH*DD*DD];           // N^T = Wk^T Wq per head [j][i]
__device__ __align__(256) __half g_gcat[DD*HH*DD];          // Ghat [o][4096]
__device__ __align__(256) __half g_th [BB*HH*SS*DD];        // T = X N^T  [B,H,S,D]
__device__ __align__(256) __half g_sch[(size_t)BB*HH*SS*SS];// scores / P
__device__ __align__(256) __half g_hh [BB*SS*HH*DD];        // Ucat [B,S,4096]
// small fp32
__device__ float g_p[HH*DD], g_r[HH*DD], g_c[HH], g_chat[DD];
__device__ float g_u[BB*HH*SS], g_v[BB*HH*SS];

// ---------------- helpers ----------------
__device__ __forceinline__ unsigned smem_u32(const void* p) {
    return (unsigned)__cvta_generic_to_shared(p);
}
__device__ __forceinline__ void cp16(void* dst, const void* src) {
    asm volatile("cp.async.cg.shared.global [%0], [%1], 16;\n"
                 :: "r"(smem_u32(dst)), "l"(src));
}

// ---------------- fp16 GEMM mainloop: 4 warps 64x64, 3-stage, 1 sync/iter ----------------
// C[128,128] += A[128,K]*B[128,K]^T, K = KT*64, arbitrary row strides lda/ldb.
template<int KT>   // KT >= 2
__device__ __forceinline__ void gemm_h(const __half* __restrict__ Ag,
                                       const __half* __restrict__ Bg,
                                       int lda, int ldb,
                                       __half* sm, float (&acc)[4][8][4])
{
    const int tid  = threadIdx.x;
    const int lane = tid & 31;
    const int warp = tid >> 5;
    const int wm = (warp & 1) * 64;
    const int wn = (warp >> 1) * 64;

#pragma unroll
    for (int mi = 0; mi < 4; mi++)
#pragma unroll
        for (int ni = 0; ni < 8; ni++)
#pragma unroll
            for (int r = 0; r < 4; r++) acc[mi][ni][r] = 0.f;

    const int srow = tid >> 3;   // 0..15
    const int sch  = tid & 7;

    auto stage = [&](int s, int kt) {
        __half* sA = sm + s * STG_H;
        __half* sB = sA + 128 * 64;
        const __half* ap = Ag + (size_t)srow * lda + kt * 64 + sch * 8;
        const __half* bp = Bg + (size_t)srow * ldb + kt * 64 + sch * 8;
#pragma unroll
        for (int i = 0; i < 8; i++) {
            int r = srow + i * 16;
            int sw = (sch ^ (r & 7)) * 8;
            cp16(sA + r * 64 + sw, ap + (size_t)(i * 16) * lda);
            cp16(sB + r * 64 + sw, bp + (size_t)(i * 16) * ldb);
        }
        asm volatile("cp.async.commit_group;\n");
    };

    stage(0, 0);
    stage(1, 1);

#pragma unroll 1
    for (int kt = 0; kt < KT; kt++) {
        if (kt < KT - 1) asm volatile("cp.async.wait_group 1;\n");
        else             asm volatile("cp.async.wait_group 0;\n");
        __syncthreads();   // all warps done reading buf (kt+2)%3 (read at kt-1)

        if (kt + 2 < KT) stage((kt + 2) % 3, kt + 2);

        const __half* sA = sm + (kt % 3) * STG_H;
        const __half* sB = sA + 128 * 64;

#pragma unroll
        for (int ks = 0; ks < 4; ks++) {
            uint32_t a[4][4];
#pragma unroll
            for (int mi = 0; mi < 4; mi++) {
                int r  = wm + mi * 16 + (lane & 15);
                int ch = 2 * ks + (lane >> 4);
                unsigned ad = smem_u32(sA + r * 64 + ((ch ^ (r & 7)) * 8));
                asm volatile("ldmatrix.sync.aligned.m8n8.x4.shared.b16 {%0,%1,%2,%3}, [%4];"
                             : "=r"(a[mi][0]), "=r"(a[mi][1]), "=r"(a[mi][2]), "=r"(a[mi][3])
                             : "r"(ad));
            }
            uint32_t b[8][2];
#pragma unroll
            for (int nj = 0; nj < 4; nj++) {
                int nr = wn + nj * 16 + ((lane >> 4) << 3) + (lane & 7);
                int ch = 2 * ks + ((lane >> 3) & 1);
                unsigned ad = smem_u32(sB + nr * 64 + ((ch ^ (nr & 7)) * 8));
                uint32_t r0, r1, r2, r3;
                asm volatile("ldmatrix.sync.aligned.m8n8.x4.shared.b16 {%0,%1,%2,%3}, [%4];"
                             : "=r"(r0), "=r"(r1), "=r"(r2), "=r"(r3) : "r"(ad));
                b[nj*2][0] = r0;  b[nj*2][1] = r1;
                b[nj*2+1][0] = r2; b[nj*2+1][1] = r3;
            }
#pragma unroll
            for (int mi = 0; mi < 4; mi++)
#pragma unroll
                for (int ni = 0; ni < 8; ni++) {
                    asm volatile(
                        "mma.sync.aligned.m16n8k16.row.col.f32.f16.f16.f32 "
                        "{%0,%1,%2,%3}, {%4,%5,%6,%7}, {%8,%9}, {%0,%1,%2,%3};"
                        : "+f"(acc[mi][ni][0]), "+f"(acc[mi][ni][1]),
                          "+f"(acc[mi][ni][2]), "+f"(acc[mi][ni][3])
                        : "r"(a[mi][0]), "r"(a[mi][1]), "r"(a[mi][2]), "r"(a[mi][3]),
                          "r"(b[ni][0]), "r"(b[ni][1]));
                }
        }
        // no trailing sync: next-iter top barrier provides the WAR guarantee
    }
}

#define EPI_ROW(wm, mi, r)  ((wm) + (mi)*16 + (lane >> 2) + (((r) >> 1) << 3))
#define EPI_COL(wn, ni, r)  ((wn) + (ni)*8 + ((lane & 3) << 1) + ((r) & 1))

// ---------------- phase 0: elementwise fp16 conversion ----------------
__global__ void k_cvt(const float* __restrict__ X,  const float* __restrict__ Wq,
                      const float* __restrict__ Wk, const float* __restrict__ Wv,
                      const float* __restrict__ Wo)
{
    const int stride = gridDim.x * blockDim.x;
    const int i0 = blockIdx.x * blockDim.x + threadIdx.x;
    for (int i = i0; i < BB*SS*DD; i += stride) g_xh[i]  = __float2half_rn(X[i]);
    for (int i = i0; i < HH*DD*DD; i += stride) g_wqh[i] = __float2half_rn(Wq[i]);
    for (int i = i0; i < HH*DD*DD; i += stride) g_wkh[i] = __float2half_rn(Wk[i]);
    for (int i = i0; i < HH*DD*DD; i += stride) g_wvh[i] = __float2half_rn(Wv[i]);
    for (int i = i0; i < DD*HH*DD; i += stride) g_woh[i] = __float2half_rn(Wo[i]);
}

// ---------------- transposes (fp16, 32x32 tiles) ----------------
__global__ void k_trw()   // grid (16,16,24), block (32,8): per-head 512x512 W^T
{
    const int m = blockIdx.z;
    const __half* src;  __half* dst;
    if (m < 8)       { src = g_wqh + (size_t)m * DD * DD;      dst = g_wqt + (size_t)m * DD * DD; }
    else if (m < 16) { src = g_wkh + (size_t)(m-8) * DD * DD;  dst = g_wkt + (size_t)(m-8) * DD * DD; }
    else             { src = g_wvh + (size_t)(m-16) * DD * DD; dst = g_wvt + (size_t)(m-16) * DD * DD; }
    __shared__ __half T[32][33];
    const int r0 = blockIdx.y * 32, c0 = blockIdx.x * 32;
    const int tx = threadIdx.x, ty = threadIdx.y;
#pragma unroll
    for (int k = 0; k < 4; k++) T[ty + 8*k][tx] = src[(size_t)(r0 + ty + 8*k) * DD + c0 + tx];
    __syncthreads();
#pragma unroll
    for (int k = 0; k < 4; k++) dst[(size_t)(c0 + ty + 8*k) * DD + r0 + tx] = T[tx][ty + 8*k];
}

__global__ void k_trx()   // grid (16,32,8): X[b] 1024x512 -> XT[b] 512x1024
{
    const int b = blockIdx.z;
    const __half* src = g_xh + (size_t)b * SS * DD;
    __half* dst = g_xt + (size_t)b * DD * SS;
    __shared__ __half T[32][33];
    const int r0 = blockIdx.y * 32, c0 = blockIdx.x * 32;   // r over S, c over D
    const int tx = threadIdx.x, ty = threadIdx.y;
#pragma unroll
    for (int k = 0; k < 4; k++) T[ty + 8*k][tx] = src[(size_t)(r0 + ty + 8*k) * DD + c0 + tx];
    __syncthreads();
#pragma unroll
    for (int k = 0; k < 4; k++) dst[(size_t)(c0 + ty + 8*k) * SS + r0 + tx] = T[tx][ty + 8*k];
}

// ---------------- small precomputes ----------------
// p_h = Wq_h^T bk_h, r_h = Wk_h^T bq_h, c_h = bq_h . bk_h   (fp32)
__global__ void k_pre(const float* __restrict__ Wq, const float* __restrict__ Wk,
                      const float* __restrict__ bq, const float* __restrict__ bk)
{
    const int h = blockIdx.x, i = threadIdx.x;
    const float* wq = Wq + (size_t)h * DD * DD;
    const float* wk = Wk + (size_t)h * DD * DD;
    float pa = 0.f, ra = 0.f;
    for (int e = 0; e < DD; e++) {
        pa += wq[(size_t)e * DD + i] * bk[h * DD + e];
        ra += wk[(size_t)e * DD + i] * bq[h * DD + e];
    }
    g_p[h * DD + i] = pa;
    g_r[h * DD + i] = ra;
    __shared__ float red[DD];
    red[i] = bq[h * DD + i] * bk[h * DD + i];
    __syncthreads();
    for (int s = DD / 2; s > 0; s >>= 1) {
        if (i < s) red[i] += red[i + s];
        __syncthreads();
    }
    if (i == 0) g_c[h] = red[0];
}

// chat[o] = sum_k Wo[o,k]*bv_flat[k] + bo[o]
__global__ void k_chat(const float* __restrict__ Wo, const float* __restrict__ bv,
                       const float* __restrict__ bo)
{
    const int o = blockIdx.x, t = threadIdx.x;
    float a = 0.f;
    for (int k = t; k < HH * DD; k += 256) a += Wo[(size_t)o * (HH*DD) + k] * bv[k];
    __shared__ float red[256];
    red[t] = a;
    __syncthreads();
    for (int s = 128; s > 0; s >>= 1) {
        if (t < s) red[t] += red[t + s];
        __syncthreads();
    }
    if (t == 0) g_chat[o] = red[0] + bo[o];
}

// u[z,s] = x_s . p_h ; v[z,s] = x_s . r_h   (one warp per token)
__global__ void k_uv()
{
    __shared__ float sp[HH * DD];
    __shared__ float sr[HH * DD];
    for (int i = threadIdx.x; i < HH * DD; i += 128) { sp[i] = g_p[i]; sr[i] = g_r[i]; }
    __syncthreads();
    const int warp = threadIdx.x >> 5, lane = threadIdx.x & 31;
    const int tok = blockIdx.x * 4 + warp;           // 0..8191
    const int b = tok >> 10, ss = tok & 1023;
    const __half* x = g_xh + (size_t)tok * DD;
    float xv[16];
#pragma unroll
    for (int k = 0; k < 16; k++) xv[k] = __half2float(x[lane + 32 * k]);
#pragma unroll
    for (int h = 0; h < HH; h++) {
        float du = 0.f, dv = 0.f;
#pragma unroll
        for (int k = 0; k < 16; k++) {
            du += xv[k] * sp[h * DD + lane + 32 * k];
            dv += xv[k] * sr[h * DD + lane + 32 * k];
        }
#pragma unroll
        for (int o = 16; o > 0; o >>= 1) {
            du += __shfl_xor_sync(0xffffffffu, du, o);
            dv += __shfl_xor_sync(0xffffffffu, dv, o);
        }
        if (lane == 0) {
            g_u[(b * HH + h) * SS + ss] = du;
            g_v[(b * HH + h) * SS + ss] = dv;
        }
    }
}

// ---------------- mgemm: z<8 -> N^T_h = Wk^T Wq ; z>=8 -> Ghat_h = Wo_h Wv_h ----------------
__global__ void __launch_bounds__(128, 2) k_mgemm()
{
    extern __shared__ __half sm[];
    const int m0 = blockIdx.x * 128, n0 = blockIdx.y * 128, z = blockIdx.z;
    float acc[4][8][4];
    const int lane = threadIdx.x & 31, warp = threadIdx.x >> 5;
    const int wm = (warp & 1) * 64, wn = (warp >> 1) * 64;

    if (z < 8) {
        const __half* A = g_wkt + (size_t)z * DD * DD + (size_t)m0 * DD;  // rows j over e
        const __half* B = g_wqt + (size_t)z * DD * DD + (size_t)n0 * DD;  // rows i over e
        gemm_h<8>(A, B, DD, DD, sm, acc);
        __half* C = g_mh + (size_t)z * DD * DD;
#pragma unroll
        for (int mi = 0; mi < 4; mi++)
#pragma unroll
            for (int ni = 0; ni < 8; ni++)
#pragma unroll
                for (int r = 0; r < 4; r++)
                    C[(size_t)(m0 + EPI_ROW(wm, mi, r)) * DD + n0 + EPI_COL(wn, ni, r)] =
                        __float2half_rn(acc[mi][ni][r]);
    } else {
        const int h = z - 8;
        const __half* A = g_woh + (size_t)m0 * (HH*DD) + h * DD;          // Wo rows o, K-slice e
        const __half* B = g_wvt + (size_t)h * DD * DD + (size_t)n0 * DD;  // rows j over e
        gemm_h<8>(A, B, HH*DD, DD, sm, acc);
#pragma unroll
        for (int mi = 0; mi < 4; mi++)
#pragma unroll
            for (int ni = 0; ni < 8; ni++)
#pragma unroll
                for (int r = 0; r < 4; r++)
                    g_gcat[(size_t)(m0 + EPI_ROW(wm, mi, r)) * (HH*DD) + h * DD + n0 + EPI_COL(wn, ni, r)] =
                        __float2half_rn(acc[mi][ni][r]);
    }
}

// ---------------- T = X N^T : grid (64,4,8) z=h ----------------
__global__ void __launch_bounds__(128, 2) k_T()
{
    extern __shared__ __half sm[];
    const int m0 = blockIdx.x * 128, n0 = blockIdx.y * 128, h = blockIdx.z;
    float acc[4][8][4];
    gemm_h<8>(g_xh + (size_t)m0 * DD,
              g_mh + (size_t)h * DD * DD + (size_t)n0 * DD, DD, DD, sm, acc);

    const int lane = threadIdx.x & 31, warp = threadIdx.x >> 5;
    const int wm = (warp & 1) * 64, wn = (warp >> 1) * 64;
#pragma unroll
    for (int mi = 0; mi < 4; mi++)
#pragma unroll
        for (int ni = 0; ni < 8; ni++)
#pragma unroll
            for (int r = 0; r < 4; r++) {
                int row = m0 + EPI_ROW(wm, mi, r);
                int col = n0 + EPI_COL(wn, ni, r);
                int b = row >> 10, s = row & 1023;
                g_th[(((size_t)(b*HH + h) * SS + s) * DD) + col] = __float2half_rn(acc[mi][ni][r]);
            }
}

// ---------------- scores = T X^T + u + v + c : grid (8,8,64) ----------------
__global__ void __launch_bounds__(128, 2) k_scores()
{
    extern __shared__ __half sm[];
    const int m0 = blockIdx.x * 128, n0 = blockIdx.y * 128, z = blockIdx.z;
    const int b = z >> 3, h = z & 7;
    float acc[4][8][4];
    gemm_h<8>(g_th + (size_t)z * SS * DD + (size_t)m0 * DD,
              g_xh + (size_t)b * SS * DD + (size_t)n0 * DD, DD, DD, sm, acc);

    __half* C = g_sch + (size_t)z * SS * SS;
    const float ch = g_c[h];
    const int lane = threadIdx.x & 31, warp = threadIdx.x >> 5;
    const int wm = (warp & 1) * 64, wn = (warp >> 1) * 64;
#pragma unroll
    for (int mi = 0; mi < 4; mi++)
#pragma unroll
        for (int ni = 0; ni < 8; ni++)
#pragma unroll
            for (int r = 0; r < 4; r++) {
                int row = m0 + EPI_ROW(wm, mi, r);
                int col = n0 + EPI_COL(wn, ni, r);
                float val = acc[mi][ni][r] + g_u[z * SS + row] + g_v[z * SS + col] + ch;
                C[(size_t)row * SS + col] = __float2half_rn(val);
            }
}

// ---------------- softmax (fp32 math, fp16 in/out) ----------------
__global__ void k_softmax()
{
    const int row  = blockIdx.x * 8 + (threadIdx.x >> 5);
    const int lane = threadIdx.x & 31;
    __half2* p2 = (__half2*)(g_sch + (size_t)row * SS);
    const float scl = 1.0f / 262144.0f;

    float v[32];
#pragma unroll
    for (int i = 0; i < 16; i++) {
        float2 t = __half22float2(p2[lane + i * 32]);
        v[2*i] = t.x * scl;  v[2*i+1] = t.y * scl;
    }
    float m = v[0];
#pragma unroll
    for (int i = 1; i < 32; i++) m = fmaxf(m, v[i]);
#pragma unroll
    for (int o = 16; o > 0; o >>= 1) m = fmaxf(m, __shfl_xor_sync(0xffffffffu, m, o));
    float s = 0.f;
#pragma unroll
    for (int i = 0; i < 32; i++) { v[i] = __expf(v[i] - m); s += v[i]; }
#pragma unroll
    for (int o = 16; o > 0; o >>= 1) s += __shfl_xor_sync(0xffffffffu, s, o);
    float inv = 1.0f / s;
#pragma unroll
    for (int i = 0; i < 16; i++)
        p2[lane + i * 32] = __floats2half2_rn(v[2*i] * inv, v[2*i+1] * inv);
}

// ---------------- U = P X  -> Ucat : grid (8,4,64) ----------------
__global__ void __launch_bounds__(128, 2) k_U()
{
    extern __shared__ __half sm[];
    const int m0 = blockIdx.x * 128, n0 = blockIdx.y * 128, z = blockIdx.z;
    const int b = z >> 3, h = z & 7;
    float acc[4][8][4];
    gemm_h<16>(g_sch + (size_t)z * SS * SS + (size_t)m0 * SS,
               g_xt  + (size_t)b * DD * SS + (size_t)n0 * SS, SS, SS, sm, acc);

    const int lane = threadIdx.x & 31, warp = threadIdx.x >> 5;
    const int wm = (warp & 1) * 64, wn = (warp >> 1) * 64;
#pragma unroll
    for (int mi = 0; mi < 4; mi++)
#pragma unroll
        for (int ni = 0; ni < 8; ni++)
#pragma unroll
            for (int r = 0; r < 4; r++) {
                int s_ = m0 + EPI_ROW(wm, mi, r);
                int j  = n0 + EPI_COL(wn, ni, r);
                g_hh[((size_t)(b * SS + s_)) * (HH*DD) + h * DD + j] =
                    __float2half_rn(acc[mi][ni][r]);
            }
}

// ---------------- out = Ucat Ghat^T + chat : grid (64,4) ----------------
__global__ void __launch_bounds__(128, 2) k_out(float* __restrict__ out)
{
    extern __shared__ __half sm[];
    const int m0 = blockIdx.x * 128, n0 = blockIdx.y * 128;
    float acc[4][8][4];
    gemm_h<64>(g_hh   + (size_t)m0 * (HH*DD),
               g_gcat + (size_t)n0 * (HH*DD), HH*DD, HH*DD, sm, acc);

    const int lane = threadIdx.x & 31, warp = threadIdx.x >> 5;
    const int wm = (warp & 1) * 64, wn = (warp >> 1) * 64;
#pragma unroll
    for (int mi = 0; mi < 4; mi++)
#pragma unroll
        for (int ni = 0; ni < 8; ni++)
#pragma unroll
            for (int r = 0; r < 4; r++) {
                int row = m0 + EPI_ROW(wm, mi, r);
                int col = n0 + EPI_COL(wn, ni, r);
                out[(size_t)row * DD + col] = acc[mi][ni][r] + g_chat[col];
            }
}

// ---------------- host launcher ----------------
extern "C" void kernel_launch(void* const* d_in, const int* in_sizes, int n_in,
                              void* d_out, int out_size)
{
    const float* X  = (const float*)d_in[0];
    const float* Wq = (const float*)d_in[1];
    const float* bq = (const float*)d_in[2];
    const float* Wk = (const float*)d_in[3];
    const float* bk = (const float*)d_in[4];
    const float* Wv = (const float*)d_in[5];
    const float* bv = (const float*)d_in[6];
    const float* Wo = (const float*)d_in[7];
    const float* bo = (const float*)d_in[8];
    float* out = (float*)d_out;

    const int SMEM = 3 * STG_H * 2;   // 98304 bytes
    cudaFuncSetAttribute(k_mgemm,  cudaFuncAttributeMaxDynamicSharedMemorySize, SMEM);
    cudaFuncSetAttribute(k_T,      cudaFuncAttributeMaxDynamicSharedMemorySize, SMEM);
    cudaFuncSetAttribute(k_scores, cudaFuncAttributeMaxDynamicSharedMemorySize, SMEM);
    cudaFuncSetAttribute(k_U,      cudaFuncAttributeMaxDynamicSharedMemorySize, SMEM);
    cudaFuncSetAttribute(k_out,    cudaFuncAttributeMaxDynamicSharedMemorySize, SMEM);

    k_cvt<<<2048, 256>>>(X, Wq, Wk, Wv, Wo);
    k_trw<<<dim3(16, 16, 24), dim3(32, 8)>>>();
    k_trx<<<dim3(16, 32, 8),  dim3(32, 8)>>>();
    k_pre<<<8, 512>>>(Wq, Wk, bq, bk);
    k_chat<<<512, 256>>>(Wo, bv, bo);
    k_mgemm<<<dim3(4, 4, 16), 128, SMEM>>>();
    k_uv<<<2048, 128>>>();
    k_T<<<dim3(64, 4, 8), 128, SMEM>>>();
    k_scores<<<dim3(8, 8, 64), 128, SMEM>>>();
    k_softmax<<<8192, 256>>>();
    k_U<<<dim3(8, 4, 64), 128, SMEM>>>();
    k_out<<<dim3(64, 4), 128, SMEM>>>(out);
}

// round 13
// speedup vs baseline: 2.8064x; 1.1493x over previous
#include <cuda_runtime.h>
#include <cuda_fp16.h>
#include <cstdint>

#define BB 8
#define SS 1024
#define DD 512
#define HH 8

#define STG_H (128*64*2)     // halves per stage (A 128x64 + B 128x64)

// ---------------- fp16 staged tensors ----------------
__device__ __align__(256) __half g_xh [BB*SS*DD];           // X [B,S,D]
__device__ __align__(256) __half g_xt [BB*DD*SS];           // X^T [B,D,S]
__device__ __align__(256) __half g_wqh[HH*DD*DD];
__device__ __align__(256) __half g_wkh[HH*DD*DD];
__device__ __align__(256) __half g_wvh[HH*DD*DD];
__device__ __align__(256) __half g_woh[DD*HH*DD];           // Wo [512,4096]
__device__ __align__(256) __half g_wqt[HH*DD*DD];           // Wq^T per head [i][e]
__device__ __align__(256) __half g_wkt[HH*DD*DD];
__device__ __align__(256) __half g_wvt[HH*DD*DD];
__device__ __align__(256) __half g_mh [HH*DD*DD];           // N^T = Wk^T Wq per head [j][i]
__device__ __align__(256) __half g_gcat[DD*HH*DD];          // Ghat [o][4096]
__device__ __align__(256) __half g_th [BB*HH*SS*DD];        // T = X N^T  [B,H,S,D]
__device__ __align__(256) __half g_sch[(size_t)BB*HH*SS*SS];// scores / P
__device__ __align__(256) __half g_hh [BB*SS*HH*DD];        // Ucat [B,S,4096]
// small fp32
__device__ float g_rpart[HH*8*DD];                           // k_pre partials
__device__ float g_r[HH*DD], g_chat[DD];
__device__ float g_v[BB*HH*SS];

// ---------------- helpers ----------------
__device__ __forceinline__ unsigned smem_u32(const void* p) {
    return (unsigned)__cvta_generic_to_shared(p);
}
__device__ __forceinline__ void cp16(void* dst, const void* src) {
    asm volatile("cp.async.cg.shared.global [%0], [%1], 16;\n"
                 :: "r"(smem_u32(dst)), "l"(src));
}

// ---------------- fp16 GEMM mainloop: 4 warps 64x64, 3-stage, 1 sync/iter ----------------
// C[128,128] += A[128,K]*B[128,K]^T, K = KT*64, arbitrary row strides lda/ldb.
template<int KT>   // KT >= 2
__device__ __forceinline__ void gemm_h(const __half* __restrict__ Ag,
                                       const __half* __restrict__ Bg,
                                       int lda, int ldb,
                                       __half* sm, float (&acc)[4][8][4])
{
    const int tid  = threadIdx.x;
    const int lane = tid & 31;
    const int warp = tid >> 5;
    const int wm = (warp & 1) * 64;
    const int wn = (warp >> 1) * 64;

#pragma unroll
    for (int mi = 0; mi < 4; mi++)
#pragma unroll
        for (int ni = 0; ni < 8; ni++)
#pragma unroll
            for (int r = 0; r < 4; r++) acc[mi][ni][r] = 0.f;

    const int srow = tid >> 3;   // 0..15
    const int sch  = tid & 7;

    auto stage = [&](int s, int kt) {
        __half* sA = sm + s * STG_H;
        __half* sB = sA + 128 * 64;
        const __half* ap = Ag + (size_t)srow * lda + kt * 64 + sch * 8;
        const __half* bp = Bg + (size_t)srow * ldb + kt * 64 + sch * 8;
#pragma unroll
        for (int i = 0; i < 8; i++) {
            int r = srow + i * 16;
            int sw = (sch ^ (r & 7)) * 8;
            cp16(sA + r * 64 + sw, ap + (size_t)(i * 16) * lda);
            cp16(sB + r * 64 + sw, bp + (size_t)(i * 16) * ldb);
        }
        asm volatile("cp.async.commit_group;\n");
    };

    stage(0, 0);
    stage(1, 1);

#pragma unroll 1
    for (int kt = 0; kt < KT; kt++) {
        if (kt < KT - 1) asm volatile("cp.async.wait_group 1;\n");
        else             asm volatile("cp.async.wait_group 0;\n");
        __syncthreads();

        if (kt + 2 < KT) stage((kt + 2) % 3, kt + 2);

        const __half* sA = sm + (kt % 3) * STG_H;
        const __half* sB = sA + 128 * 64;

#pragma unroll
        for (int ks = 0; ks < 4; ks++) {
            uint32_t a[4][4];
#pragma unroll
            for (int mi = 0; mi < 4; mi++) {
                int r  = wm + mi * 16 + (lane & 15);
                int ch = 2 * ks + (lane >> 4);
                unsigned ad = smem_u32(sA + r * 64 + ((ch ^ (r & 7)) * 8));
                asm volatile("ldmatrix.sync.aligned.m8n8.x4.shared.b16 {%0,%1,%2,%3}, [%4];"
                             : "=r"(a[mi][0]), "=r"(a[mi][1]), "=r"(a[mi][2]), "=r"(a[mi][3])
                             : "r"(ad));
            }
            uint32_t b[8][2];
#pragma unroll
            for (int nj = 0; nj < 4; nj++) {
                int nr = wn + nj * 16 + ((lane >> 4) << 3) + (lane & 7);
                int ch = 2 * ks + ((lane >> 3) & 1);
                unsigned ad = smem_u32(sB + nr * 64 + ((ch ^ (nr & 7)) * 8));
                uint32_t r0, r1, r2, r3;
                asm volatile("ldmatrix.sync.aligned.m8n8.x4.shared.b16 {%0,%1,%2,%3}, [%4];"
                             : "=r"(r0), "=r"(r1), "=r"(r2), "=r"(r3) : "r"(ad));
                b[nj*2][0] = r0;  b[nj*2][1] = r1;
                b[nj*2+1][0] = r2; b[nj*2+1][1] = r3;
            }
#pragma unroll
            for (int mi = 0; mi < 4; mi++)
#pragma unroll
                for (int ni = 0; ni < 8; ni++) {
                    asm volatile(
                        "mma.sync.aligned.m16n8k16.row.col.f32.f16.f16.f32 "
                        "{%0,%1,%2,%3}, {%4,%5,%6,%7}, {%8,%9}, {%0,%1,%2,%3};"
                        : "+f"(acc[mi][ni][0]), "+f"(acc[mi][ni][1]),
                          "+f"(acc[mi][ni][2]), "+f"(acc[mi][ni][3])
                        : "r"(a[mi][0]), "r"(a[mi][1]), "r"(a[mi][2]), "r"(a[mi][3]),
                          "r"(b[ni][0]), "r"(b[ni][1]));
                }
        }
    }
}

#define EPI_ROW(wm, mi, r)  ((wm) + (mi)*16 + (lane >> 2) + (((r) >> 1) << 3))
#define EPI_COL(wn, ni, r)  ((wn) + (ni)*8 + ((lane & 3) << 1) + ((r) & 1))

// ---------------- phase 0: elementwise fp16 conversion ----------------
__global__ void k_cvt(const float* __restrict__ X,  const float* __restrict__ Wq,
                      const float* __restrict__ Wk, const float* __restrict__ Wv,
                      const float* __restrict__ Wo)
{
    const int stride = gridDim.x * blockDim.x;
    const int i0 = blockIdx.x * blockDim.x + threadIdx.x;
    for (int i = i0; i < BB*SS*DD; i += stride) g_xh[i]  = __float2half_rn(X[i]);
    for (int i = i0; i < HH*DD*DD; i += stride) g_wqh[i] = __float2half_rn(Wq[i]);
    for (int i = i0; i < HH*DD*DD; i += stride) g_wkh[i] = __float2half_rn(Wk[i]);
    for (int i = i0; i < HH*DD*DD; i += stride) g_wvh[i] = __float2half_rn(Wv[i]);
    for (int i = i0; i < DD*HH*DD; i += stride) g_woh[i] = __float2half_rn(Wo[i]);
}

// ---------------- transposes (fp16, 32x32 tiles) ----------------
__global__ void k_trw()   // grid (16,16,24), block (32,8): per-head 512x512 W^T
{
    const int m = blockIdx.z;
    const __half* src;  __half* dst;
    if (m < 8)       { src = g_wqh + (size_t)m * DD * DD;      dst = g_wqt + (size_t)m * DD * DD; }
    else if (m < 16) { src = g_wkh + (size_t)(m-8) * DD * DD;  dst = g_wkt + (size_t)(m-8) * DD * DD; }
    else             { src = g_wvh + (size_t)(m-16) * DD * DD; dst = g_wvt + (size_t)(m-16) * DD * DD; }
    __shared__ __half T[32][33];
    const int r0 = blockIdx.y * 32, c0 = blockIdx.x * 32;
    const int tx = threadIdx.x, ty = threadIdx.y;
#pragma unroll
    for (int k = 0; k < 4; k++) T[ty + 8*k][tx] = src[(size_t)(r0 + ty + 8*k) * DD + c0 + tx];
    __syncthreads();
#pragma unroll
    for (int k = 0; k < 4; k++) dst[(size_t)(c0 + ty + 8*k) * DD + r0 + tx] = T[tx][ty + 8*k];
}

__global__ void k_trx()   // grid (16,32,8): X[b] 1024x512 -> XT[b] 512x1024
{
    const int b = blockIdx.z;
    const __half* src = g_xh + (size_t)b * SS * DD;
    __half* dst = g_xt + (size_t)b * DD * SS;
    __shared__ __half T[32][33];
    const int r0 = blockIdx.y * 32, c0 = blockIdx.x * 32;   // r over S, c over D
    const int tx = threadIdx.x, ty = threadIdx.y;
#pragma unroll
    for (int k = 0; k < 4; k++) T[ty + 8*k][tx] = src[(size_t)(r0 + ty + 8*k) * DD + c0 + tx];
    __syncthreads();
#pragma unroll
    for (int k = 0; k < 4; k++) dst[(size_t)(c0 + ty + 8*k) * SS + r0 + tx] = T[tx][ty + 8*k];
}

// ---------------- k_pre (parallelized): r_h = Wk_h^T bq_h ----------------
// stage 1: grid (8 heads, 8 e-chunks), block 512: partials over 64 e-values
__global__ void k_pre1(const float* __restrict__ Wk, const float* __restrict__ bq)
{
    const int h = blockIdx.x, ec = blockIdx.y, i = threadIdx.x;
    const float* wk = Wk + (size_t)h * DD * DD;
    float ra = 0.f;
    const int e0 = ec * 64;
#pragma unroll 8
    for (int e = e0; e < e0 + 64; e++)
        ra += wk[(size_t)e * DD + i] * bq[h * DD + e];
    g_rpart[(h * 8 + ec) * DD + i] = ra;
}
// stage 2: reduce 8 partials
__global__ void k_pre2()
{
    const int h = blockIdx.x, i = threadIdx.x;
    float a = 0.f;
#pragma unroll
    for (int ec = 0; ec < 8; ec++) a += g_rpart[(h * 8 + ec) * DD + i];
    g_r[h * DD + i] = a;
}

// chat[o] = sum_k Wo[o,k]*bv_flat[k] + bo[o]
__global__ void k_chat(const float* __restrict__ Wo, const float* __restrict__ bv,
                       const float* __restrict__ bo)
{
    const int o = blockIdx.x, t = threadIdx.x;
    float a = 0.f;
    for (int k = t; k < HH * DD; k += 256) a += Wo[(size_t)o * (HH*DD) + k] * bv[k];
    __shared__ float red[256];
    red[t] = a;
    __syncthreads();
    for (int s = 128; s > 0; s >>= 1) {
        if (t < s) red[t] += red[t + s];
        __syncthreads();
    }
    if (t == 0) g_chat[o] = red[0] + bo[o];
}

// v[z,t] = x_t . r_h   (one warp per token, 8 heads each)
__global__ void k_v()
{
    __shared__ float sr[HH * DD];
    for (int i = threadIdx.x; i < HH * DD; i += 128) sr[i] = g_r[i];
    __syncthreads();
    const int warp = threadIdx.x >> 5, lane = threadIdx.x & 31;
    const int tok = blockIdx.x * 4 + warp;           // 0..8191
    const int b = tok >> 10, ss = tok & 1023;
    const __half* x = g_xh + (size_t)tok * DD;
    float xv[16];
#pragma unroll
    for (int k = 0; k < 16; k++) xv[k] = __half2float(x[lane + 32 * k]);
#pragma unroll
    for (int h = 0; h < HH; h++) {
        float dv = 0.f;
#pragma unroll
        for (int k = 0; k < 16; k++) dv += xv[k] * sr[h * DD + lane + 32 * k];
#pragma unroll
        for (int o = 16; o > 0; o >>= 1) dv += __shfl_xor_sync(0xffffffffu, dv, o);
        if (lane == 0) g_v[(b * HH + h) * SS + ss] = dv;
    }
}

// ---------------- mgemm: z<8 -> N^T_h = Wk^T Wq ; z>=8 -> Ghat_h = Wo_h Wv_h ----------------
__global__ void __launch_bounds__(128, 2) k_mgemm()
{
    extern __shared__ __half sm[];
    const int m0 = blockIdx.x * 128, n0 = blockIdx.y * 128, z = blockIdx.z;
    float acc[4][8][4];
    const int lane = threadIdx.x & 31, warp = threadIdx.x >> 5;
    const int wm = (warp & 1) * 64, wn = (warp >> 1) * 64;

    if (z < 8) {
        const __half* A = g_wkt + (size_t)z * DD * DD + (size_t)m0 * DD;  // rows j over e
        const __half* B = g_wqt + (size_t)z * DD * DD + (size_t)n0 * DD;  // rows i over e
        gemm_h<8>(A, B, DD, DD, sm, acc);
        __half* C = g_mh + (size_t)z * DD * DD;
#pragma unroll
        for (int mi = 0; mi < 4; mi++)
#pragma unroll
            for (int ni = 0; ni < 8; ni++)
#pragma unroll
                for (int r = 0; r < 4; r++)
                    C[(size_t)(m0 + EPI_ROW(wm, mi, r)) * DD + n0 + EPI_COL(wn, ni, r)] =
                        __float2half_rn(acc[mi][ni][r]);
    } else {
        const int h = z - 8;
        const __half* A = g_woh + (size_t)m0 * (HH*DD) + h * DD;          // Wo rows o, K-slice e
        const __half* B = g_wvt + (size_t)h * DD * DD + (size_t)n0 * DD;  // rows j over e
        gemm_h<8>(A, B, HH*DD, DD, sm, acc);
#pragma unroll
        for (int mi = 0; mi < 4; mi++)
#pragma unroll
            for (int ni = 0; ni < 8; ni++)
#pragma unroll
                for (int r = 0; r < 4; r++)
                    g_gcat[(size_t)(m0 + EPI_ROW(wm, mi, r)) * (HH*DD) + h * DD + n0 + EPI_COL(wn, ni, r)] =
                        __float2half_rn(acc[mi][ni][r]);
    }
}

// ---------------- T = X N^T : grid (64,4,8) z=h ----------------
__global__ void __launch_bounds__(128, 2) k_T()
{
    extern __shared__ __half sm[];
    const int m0 = blockIdx.x * 128, n0 = blockIdx.y * 128, h = blockIdx.z;
    float acc[4][8][4];
    gemm_h<8>(g_xh + (size_t)m0 * DD,
              g_mh + (size_t)h * DD * DD + (size_t)n0 * DD, DD, DD, sm, acc);

    const int lane = threadIdx.x & 31, warp = threadIdx.x >> 5;
    const int wm = (warp & 1) * 64, wn = (warp >> 1) * 64;
#pragma unroll
    for (int mi = 0; mi < 4; mi++)
#pragma unroll
        for (int ni = 0; ni < 8; ni++)
#pragma unroll
            for (int r = 0; r < 4; r++) {
                int row = m0 + EPI_ROW(wm, mi, r);
                int col = n0 + EPI_COL(wn, ni, r);
                int b = row >> 10, s = row & 1023;
                g_th[(((size_t)(b*HH + h) * SS + s) * DD) + col] = __float2half_rn(acc[mi][ni][r]);
            }
}

// ---------------- scores = T X^T + v[col] : grid (8,8,64) ----------------
// (row-constant terms x_s.Wq^T bk and bq.bk cancel under softmax; omitted)
__global__ void __launch_bounds__(128, 2) k_scores()
{
    extern __shared__ __half sm[];
    const int m0 = blockIdx.x * 128, n0 = blockIdx.y * 128, z = blockIdx.z;
    const int b = z >> 3;
    float acc[4][8][4];
    gemm_h<8>(g_th + (size_t)z * SS * DD + (size_t)m0 * DD,
              g_xh + (size_t)b * SS * DD + (size_t)n0 * DD, DD, DD, sm, acc);

    __half* C = g_sch + (size_t)z * SS * SS;
    const int lane = threadIdx.x & 31, warp = threadIdx.x >> 5;
    const int wm = (warp & 1) * 64, wn = (warp >> 1) * 64;
#pragma unroll
    for (int mi = 0; mi < 4; mi++)
#pragma unroll
        for (int ni = 0; ni < 8; ni++)
#pragma unroll
            for (int r = 0; r < 4; r++) {
                int row = m0 + EPI_ROW(wm, mi, r);
                int col = n0 + EPI_COL(wn, ni, r);
                float val = acc[mi][ni][r] + g_v[z * SS + col];
                C[(size_t)row * SS + col] = __float2half_rn(val);
            }
}

// ---------------- softmax (fp32 math, fp16 in/out) ----------------
__global__ void k_softmax()
{
    const int row  = blockIdx.x * 8 + (threadIdx.x >> 5);
    const int lane = threadIdx.x & 31;
    __half2* p2 = (__half2*)(g_sch + (size_t)row * SS);
    const float scl = 1.0f / 262144.0f;

    float v[32];
#pragma unroll
    for (int i = 0; i < 16; i++) {
        float2 t = __half22float2(p2[lane + i * 32]);
        v[2*i] = t.x * scl;  v[2*i+1] = t.y * scl;
    }
    float m = v[0];
#pragma unroll
    for (int i = 1; i < 32; i++) m = fmaxf(m, v[i]);
#pragma unroll
    for (int o = 16; o > 0; o >>= 1) m = fmaxf(m, __shfl_xor_sync(0xffffffffu, m, o));
    float s = 0.f;
#pragma unroll
    for (int i = 0; i < 32; i++) { v[i] = __expf(v[i] - m); s += v[i]; }
#pragma unroll
    for (int o = 16; o > 0; o >>= 1) s += __shfl_xor_sync(0xffffffffu, s, o);
    float inv = 1.0f / s;
#pragma unroll
    for (int i = 0; i < 16; i++)
        p2[lane + i * 32] = __floats2half2_rn(v[2*i] * inv, v[2*i+1] * inv);
}

// ---------------- U = P X  -> Ucat : grid (8,4,64) ----------------
__global__ void __launch_bounds__(128, 2) k_U()
{
    extern __shared__ __half sm[];
    const int m0 = blockIdx.x * 128, n0 = blockIdx.y * 128, z = blockIdx.z;
    const int b = z >> 3, h = z & 7;
    float acc[4][8][4];
    gemm_h<16>(g_sch + (size_t)z * SS * SS + (size_t)m0 * SS,
               g_xt  + (size_t)b * DD * SS + (size_t)n0 * SS, SS, SS, sm, acc);

    const int lane = threadIdx.x & 31, warp = threadIdx.x >> 5;
    const int wm = (warp & 1) * 64, wn = (warp >> 1) * 64;
#pragma unroll
    for (int mi = 0; mi < 4; mi++)
#pragma unroll
        for (int ni = 0; ni < 8; ni++)
#pragma unroll
            for (int r = 0; r < 4; r++) {
                int s_ = m0 + EPI_ROW(wm, mi, r);
                int j  = n0 + EPI_COL(wn, ni, r);
                g_hh[((size_t)(b * SS + s_)) * (HH*DD) + h * DD + j] =
                    __float2half_rn(acc[mi][ni][r]);
            }
}

// ---------------- out = Ucat Ghat^T + chat : grid (64,4) ----------------
__global__ void __launch_bounds__(128, 2) k_out(float* __restrict__ out)
{
    extern __shared__ __half sm[];
    const int m0 = blockIdx.x * 128, n0 = blockIdx.y * 128;
    float acc[4][8][4];
    gemm_h<64>(g_hh   + (size_t)m0 * (HH*DD),
               g_gcat + (size_t)n0 * (HH*DD), HH*DD, HH*DD, sm, acc);

    const int lane = threadIdx.x & 31, warp = threadIdx.x >> 5;
    const int wm = (warp & 1) * 64, wn = (warp >> 1) * 64;
#pragma unroll
    for (int mi = 0; mi < 4; mi++)
#pragma unroll
        for (int ni = 0; ni < 8; ni++)
#pragma unroll
            for (int r = 0; r < 4; r++) {
                int row = m0 + EPI_ROW(wm, mi, r);
                int col = n0 + EPI_COL(wn, ni, r);
                out[(size_t)row * DD + col] = acc[mi][ni][r] + g_chat[col];
            }
}

// ---------------- host launcher ----------------
extern "C" void kernel_launch(void* const* d_in, const int* in_sizes, int n_in,
                              void* d_out, int out_size)
{
    const float* X  = (const float*)d_in[0];
    const float* Wq = (const float*)d_in[1];
    const float* bq = (const float*)d_in[2];
    const float* Wk = (const float*)d_in[3];
    const float* bk = (const float*)d_in[4];
    const float* Wv = (const float*)d_in[5];
    const float* bv = (const float*)d_in[6];
    const float* Wo = (const float*)d_in[7];
    const float* bo = (const float*)d_in[8];
    float* out = (float*)d_out;
    (void)bk;

    const int SMEM = 3 * STG_H * 2;   // 98304 bytes
    cudaFuncSetAttribute(k_mgemm,  cudaFuncAttributeMaxDynamicSharedMemorySize, SMEM);
    cudaFuncSetAttribute(k_T,      cudaFuncAttributeMaxDynamicSharedMemorySize, SMEM);
    cudaFuncSetAttribute(k_scores, cudaFuncAttributeMaxDynamicSharedMemorySize, SMEM);
    cudaFuncSetAttribute(k_U,      cudaFuncAttributeMaxDynamicSharedMemorySize, SMEM);
    cudaFuncSetAttribute(k_out,    cudaFuncAttributeMaxDynamicSharedMemorySize, SMEM);

    k_cvt<<<2048, 256>>>(X, Wq, Wk, Wv, Wo);
    k_trw<<<dim3(16, 16, 24), dim3(32, 8)>>>();
    k_trx<<<dim3(16, 32, 8),  dim3(32, 8)>>>();
    k_pre1<<<dim3(8, 8), 512>>>(Wk, bq);
    k_pre2<<<8, 512>>>();
    k_chat<<<512, 256>>>(Wo, bv, bo);
    k_mgemm<<<dim3(4, 4, 16), 128, SMEM>>>();
    k_v<<<2048, 128>>>();
    k_T<<<dim3(64, 4, 8), 128, SMEM>>>();
    k_scores<<<dim3(8, 8, 64), 128, SMEM>>>();
    k_softmax<<<8192, 256>>>();
    k_U<<<dim3(8, 4, 64), 128, SMEM>>>();
    k_out<<<dim3(64, 4), 128, SMEM>>>(out);
}

// round 14
// speedup vs baseline: 3.6985x; 1.3179x over previous
#include <cuda_runtime.h>
#include <cuda_fp16.h>
#include <cstdint>

#define BB 8
#define SS 1024
#define DD 512
#define HH 8

#define STG_H (128*64*2)     // halves per stage (A 128x64 + B 128x64)

// ---------------- fp16 staged tensors ----------------
__device__ __align__(256) __half g_xh [BB*SS*DD];           // X [B,S,D]
__device__ __align__(256) __half g_xt [BB*DD*SS];           // X^T [B,D,S]
__device__ __align__(256) __half g_wqh[HH*DD*DD];
__device__ __align__(256) __half g_wkh[HH*DD*DD];
__device__ __align__(256) __half g_wvh[HH*DD*DD];
__device__ __align__(256) __half g_woh[DD*HH*DD];           // Wo [512,4096]
__device__ __align__(256) __half g_wqt[HH*DD*DD];
__device__ __align__(256) __half g_wkt[HH*DD*DD];
__device__ __align__(256) __half g_wvt[HH*DD*DD];
__device__ __align__(256) __half g_mh [HH*DD*DD];           // N^T per head  [j][i]
__device__ __align__(256) __half g_nh [HH*DD*DD];           // N   per head  [i][j]
__device__ __align__(256) __half g_gcat[DD*HH*DD];          // Ghat [o][4096]
__device__ __align__(256) __half g_g1 [BB*DD*DD];           // G1_b = X^T X  [e][e']
__device__ __align__(256) __half g_ft [(size_t)BB*HH*DD*DD];// FT_{z}[j][i] = (N G1)^T
__device__ __align__(256) __half g_hh [BB*SS*HH*DD];        // Ucat [B,S,4096]
// small fp32
__device__ float g_rpart[HH*8*DD];
__device__ float g_r[HH*DD], g_chat[DD];
__device__ float g_v[BB*HH*SS];                              // v[z][t] = x_t . r_h
__device__ float g_vbar[BB*HH];
__device__ float g_cs[BB*DD];                                // colsum_b[j]
__device__ float g_w2[BB*HH*DD];                             // w2[z][i] = N x̄
__device__ float g_rm[BB*HH*SS];                             // row-mean of centered scores
__device__ float g_vx[BB*HH*DD];                             // vX[z][j]

// ---------------- helpers ----------------
__device__ __forceinline__ unsigned smem_u32(const void* p) {
    return (unsigned)__cvta_generic_to_shared(p);
}
__device__ __forceinline__ void cp16(void* dst, const void* src) {
    asm volatile("cp.async.cg.shared.global [%0], [%1], 16;\n"
                 :: "r"(smem_u32(dst)), "l"(src));
}

// ---------------- fp16 GEMM mainloop: 4 warps 64x64, 3-stage, 1 sync/iter ----------------
template<int KT>
__device__ __forceinline__ void gemm_h(const __half* __restrict__ Ag,
                                       const __half* __restrict__ Bg,
                                       int lda, int ldb,
                                       __half* sm, float (&acc)[4][8][4])
{
    const int tid  = threadIdx.x;
    const int lane = tid & 31;
    const int warp = tid >> 5;
    const int wm = (warp & 1) * 64;
    const int wn = (warp >> 1) * 64;

#pragma unroll
    for (int mi = 0; mi < 4; mi++)
#pragma unroll
        for (int ni = 0; ni < 8; ni++)
#pragma unroll
            for (int r = 0; r < 4; r++) acc[mi][ni][r] = 0.f;

    const int srow = tid >> 3;
    const int sch  = tid & 7;

    auto stage = [&](int s, int kt) {
        __half* sA = sm + s * STG_H;
        __half* sB = sA + 128 * 64;
        const __half* ap = Ag + (size_t)srow * lda + kt * 64 + sch * 8;
        const __half* bp = Bg + (size_t)srow * ldb + kt * 64 + sch * 8;
#pragma unroll
        for (int i = 0; i < 8; i++) {
            int r = srow + i * 16;
            int sw = (sch ^ (r & 7)) * 8;
            cp16(sA + r * 64 + sw, ap + (size_t)(i * 16) * lda);
            cp16(sB + r * 64 + sw, bp + (size_t)(i * 16) * ldb);
        }
        asm volatile("cp.async.commit_group;\n");
    };

    stage(0, 0);
    stage(1, 1);

#pragma unroll 1
    for (int kt = 0; kt < KT; kt++) {
        if (kt < KT - 1) asm volatile("cp.async.wait_group 1;\n");
        else             asm volatile("cp.async.wait_group 0;\n");
        __syncthreads();

        if (kt + 2 < KT) stage((kt + 2) % 3, kt + 2);

        const __half* sA = sm + (kt % 3) * STG_H;
        const __half* sB = sA + 128 * 64;

#pragma unroll
        for (int ks = 0; ks < 4; ks++) {
            uint32_t a[4][4];
#pragma unroll
            for (int mi = 0; mi < 4; mi++) {
                int r  = wm + mi * 16 + (lane & 15);
                int ch = 2 * ks + (lane >> 4);
                unsigned ad = smem_u32(sA + r * 64 + ((ch ^ (r & 7)) * 8));
                asm volatile("ldmatrix.sync.aligned.m8n8.x4.shared.b16 {%0,%1,%2,%3}, [%4];"
                             : "=r"(a[mi][0]), "=r"(a[mi][1]), "=r"(a[mi][2]), "=r"(a[mi][3])
                             : "r"(ad));
            }
            uint32_t b[8][2];
#pragma unroll
            for (int nj = 0; nj < 4; nj++) {
                int nr = wn + nj * 16 + ((lane >> 4) << 3) + (lane & 7);
                int ch = 2 * ks + ((lane >> 3) & 1);
                unsigned ad = smem_u32(sB + nr * 64 + ((ch ^ (nr & 7)) * 8));
                uint32_t r0, r1, r2, r3;
                asm volatile("ldmatrix.sync.aligned.m8n8.x4.shared.b16 {%0,%1,%2,%3}, [%4];"
                             : "=r"(r0), "=r"(r1), "=r"(r2), "=r"(r3) : "r"(ad));
                b[nj*2][0] = r0;  b[nj*2][1] = r1;
                b[nj*2+1][0] = r2; b[nj*2+1][1] = r3;
            }
#pragma unroll
            for (int mi = 0; mi < 4; mi++)
#pragma unroll
                for (int ni = 0; ni < 8; ni++) {
                    asm volatile(
                        "mma.sync.aligned.m16n8k16.row.col.f32.f16.f16.f32 "
                        "{%0,%1,%2,%3}, {%4,%5,%6,%7}, {%8,%9}, {%0,%1,%2,%3};"
                        : "+f"(acc[mi][ni][0]), "+f"(acc[mi][ni][1]),
                          "+f"(acc[mi][ni][2]), "+f"(acc[mi][ni][3])
                        : "r"(a[mi][0]), "r"(a[mi][1]), "r"(a[mi][2]), "r"(a[mi][3]),
                          "r"(b[ni][0]), "r"(b[ni][1]));
                }
        }
    }
}

#define EPI_ROW(wm, mi, r)  ((wm) + (mi)*16 + (lane >> 2) + (((r) >> 1) << 3))
#define EPI_COL(wn, ni, r)  ((wn) + (ni)*8 + ((lane & 3) << 1) + ((r) & 1))

// ---------------- phase 0: fp16 conversion ----------------
__global__ void k_cvt(const float* __restrict__ X,  const float* __restrict__ Wq,
                      const float* __restrict__ Wk, const float* __restrict__ Wv,
                      const float* __restrict__ Wo)
{
    const int stride = gridDim.x * blockDim.x;
    const int i0 = blockIdx.x * blockDim.x + threadIdx.x;
    for (int i = i0; i < BB*SS*DD; i += stride) g_xh[i]  = __float2half_rn(X[i]);
    for (int i = i0; i < HH*DD*DD; i += stride) g_wqh[i] = __float2half_rn(Wq[i]);
    for (int i = i0; i < HH*DD*DD; i += stride) g_wkh[i] = __float2half_rn(Wk[i]);
    for (int i = i0; i < HH*DD*DD; i += stride) g_wvh[i] = __float2half_rn(Wv[i]);
    for (int i = i0; i < DD*HH*DD; i += stride) g_woh[i] = __float2half_rn(Wo[i]);
}

// ---------------- transposes ----------------
__global__ void k_trw()
{
    const int m = blockIdx.z;
    const __half* src;  __half* dst;
    if (m < 8)       { src = g_wqh + (size_t)m * DD * DD;      dst = g_wqt + (size_t)m * DD * DD; }
    else if (m < 16) { src = g_wkh + (size_t)(m-8) * DD * DD;  dst = g_wkt + (size_t)(m-8) * DD * DD; }
    else             { src = g_wvh + (size_t)(m-16) * DD * DD; dst = g_wvt + (size_t)(m-16) * DD * DD; }
    __shared__ __half T[32][33];
    const int r0 = blockIdx.y * 32, c0 = blockIdx.x * 32;
    const int tx = threadIdx.x, ty = threadIdx.y;
#pragma unroll
    for (int k = 0; k < 4; k++) T[ty + 8*k][tx] = src[(size_t)(r0 + ty + 8*k) * DD + c0 + tx];
    __syncthreads();
#pragma unroll
    for (int k = 0; k < 4; k++) dst[(size_t)(c0 + ty + 8*k) * DD + r0 + tx] = T[tx][ty + 8*k];
}

__global__ void k_trx()
{
    const int b = blockIdx.z;
    const __half* src = g_xh + (size_t)b * SS * DD;
    __half* dst = g_xt + (size_t)b * DD * SS;
    __shared__ __half T[32][33];
    const int r0 = blockIdx.y * 32, c0 = blockIdx.x * 32;
    const int tx = threadIdx.x, ty = threadIdx.y;
#pragma unroll
    for (int k = 0; k < 4; k++) T[ty + 8*k][tx] = src[(size_t)(r0 + ty + 8*k) * DD + c0 + tx];
    __syncthreads();
#pragma unroll
    for (int k = 0; k < 4; k++) dst[(size_t)(c0 + ty + 8*k) * SS + r0 + tx] = T[tx][ty + 8*k];
}

// ---------------- r_h = Wk_h^T bq_h ----------------
__global__ void k_pre1(const float* __restrict__ Wk, const float* __restrict__ bq)
{
    const int h = blockIdx.x, ec = blockIdx.y, i = threadIdx.x;
    const float* wk = Wk + (size_t)h * DD * DD;
    float ra = 0.f;
    const int e0 = ec * 64;
#pragma unroll 8
    for (int e = e0; e < e0 + 64; e++)
        ra += wk[(size_t)e * DD + i] * bq[h * DD + e];
    g_rpart[(h * 8 + ec) * DD + i] = ra;
}
__global__ void k_pre2()
{
    const int h = blockIdx.x, i = threadIdx.x;
    float a = 0.f;
#pragma unroll
    for (int ec = 0; ec < 8; ec++) a += g_rpart[(h * 8 + ec) * DD + i];
    g_r[h * DD + i] = a;
}

// chat[o] = Wo[o,:].bv + bo[o]
__global__ void k_chat(const float* __restrict__ Wo, const float* __restrict__ bv,
                       const float* __restrict__ bo)
{
    const int o = blockIdx.x, t = threadIdx.x;
    float a = 0.f;
    for (int k = t; k < HH * DD; k += 256) a += Wo[(size_t)o * (HH*DD) + k] * bv[k];
    __shared__ float red[256];
    red[t] = a;
    __syncthreads();
    for (int s = 128; s > 0; s >>= 1) {
        if (t < s) red[t] += red[t + s];
        __syncthreads();
    }
    if (t == 0) g_chat[o] = red[0] + bo[o];
}

// v[z][t] = x_t . r_h
__global__ void k_v()
{
    __shared__ float sr[HH * DD];
    for (int i = threadIdx.x; i < HH * DD; i += 128) sr[i] = g_r[i];
    __syncthreads();
    const int warp = threadIdx.x >> 5, lane = threadIdx.x & 31;
    const int tok = blockIdx.x * 4 + warp;
    const int b = tok >> 10, ss = tok & 1023;
    const __half* x = g_xh + (size_t)tok * DD;
    float xv[16];
#pragma unroll
    for (int k = 0; k < 16; k++) xv[k] = __half2float(x[lane + 32 * k]);
#pragma unroll
    for (int h = 0; h < HH; h++) {
        float dv = 0.f;
#pragma unroll
        for (int k = 0; k < 16; k++) dv += xv[k] * sr[h * DD + lane + 32 * k];
#pragma unroll
        for (int o = 16; o > 0; o >>= 1) dv += __shfl_xor_sync(0xffffffffu, dv, o);
        if (lane == 0) g_v[(b * HH + h) * SS + ss] = dv;
    }
}

// vbar[z] = mean_t v[z][t]
__global__ void k_vbar()
{
    const int z = blockIdx.x, t = threadIdx.x;
    float a = g_v[z * SS + t] + g_v[z * SS + t + 256] +
              g_v[z * SS + t + 512] + g_v[z * SS + t + 768];
    __shared__ float red[256];
    red[t] = a;
    __syncthreads();
    for (int s = 128; s > 0; s >>= 1) {
        if (t < s) red[t] += red[t + s];
        __syncthreads();
    }
    if (t == 0) g_vbar[z] = red[0] * (1.0f / SS);
}

// colsum_b[j] = sum_t X[b][t][j]
__global__ void k_colsum()
{
    const int b = blockIdx.x;
    const int j = blockIdx.y * 128 + threadIdx.x;
    const __half* x = g_xh + (size_t)b * SS * DD + j;
    float a = 0.f;
    for (int t = 0; t < SS; t++) a += __half2float(x[(size_t)t * DD]);
    g_cs[b * DD + j] = a;
}

// vX[z][j] = sum_t v[z][t] * X[b][t][j]
__global__ void k_vx()
{
    const int z = blockIdx.x, b = z >> 3;
    const int j = blockIdx.y * 128 + threadIdx.x;
    __shared__ float sv[SS];
    for (int i = threadIdx.x; i < SS; i += 128) sv[i] = g_v[z * SS + i];
    __syncthreads();
    const __half* x = g_xh + (size_t)b * SS * DD + j;
    float a = 0.f;
    for (int t = 0; t < SS; t++) a += sv[t] * __half2float(x[(size_t)t * DD]);
    g_vx[z * DD + j] = a;
}

// w2[z][i] = sum_e N_h[i][e] * xbar_b[e]
__global__ void k_w2()
{
    const int z = blockIdx.x, b = z >> 3, h = z & 7;
    const int i = threadIdx.x;
    __shared__ float sx[DD];
    for (int e = threadIdx.x; e < DD; e += 512) sx[e] = g_cs[b * DD + e] * (1.0f / SS);
    __syncthreads();
    const __half* nrow = g_nh + (size_t)h * DD * DD + (size_t)i * DD;
    float a = 0.f;
#pragma unroll 8
    for (int e = 0; e < DD; e++) a += __half2float(nrow[e]) * sx[e];
    g_w2[z * DD + i] = a;
}

// rm[z][s] = (x_s . w2[z] + vbar[z]) / D^2
__global__ void k_rm()
{
    const int warp = threadIdx.x >> 5, lane = threadIdx.x & 31;
    const int tok = blockIdx.x * 4 + warp;
    const int b = tok >> 10, ss = tok & 1023;
    __shared__ float sw[HH * DD];
    for (int i = threadIdx.x; i < HH * DD; i += 128) sw[i] = g_w2[(b * HH) * DD + i];
    __syncthreads();
    const __half* x = g_xh + (size_t)tok * DD;
    float xv[16];
#pragma unroll
    for (int k = 0; k < 16; k++) xv[k] = __half2float(x[lane + 32 * k]);
    const float invD2 = 1.0f / 262144.0f;
#pragma unroll
    for (int h = 0; h < HH; h++) {
        float d = 0.f;
#pragma unroll
        for (int k = 0; k < 16; k++) d += xv[k] * sw[h * DD + lane + 32 * k];
#pragma unroll
        for (int o = 16; o > 0; o >>= 1) d += __shfl_xor_sync(0xffffffffu, d, o);
        if (lane == 0)
            g_rm[(b * HH + h) * SS + ss] = (d + g_vbar[b * HH + h]) * invD2;
    }
}

// ---------------- mgemm: z<8 -> N (both orientations); z>=8 -> Ghat ----------------
__global__ void __launch_bounds__(128, 2) k_mgemm()
{
    extern __shared__ __half sm[];
    const int m0 = blockIdx.x * 128, n0 = blockIdx.y * 128, z = blockIdx.z;
    float acc[4][8][4];
    const int lane = threadIdx.x & 31, warp = threadIdx.x >> 5;
    const int wm = (warp & 1) * 64, wn = (warp >> 1) * 64;

    if (z < 8) {
        const __half* A = g_wkt + (size_t)z * DD * DD + (size_t)m0 * DD;  // rows j over e
        const __half* B = g_wqt + (size_t)z * DD * DD + (size_t)n0 * DD;  // rows i over e
        gemm_h<8>(A, B, DD, DD, sm, acc);
        __half* Cm = g_mh + (size_t)z * DD * DD;   // [j][i] = N^T
        __half* Cn = g_nh + (size_t)z * DD * DD;   // [i][j] = N
#pragma unroll
        for (int mi = 0; mi < 4; mi++)
#pragma unroll
            for (int ni = 0; ni < 8; ni++)
#pragma unroll
                for (int r = 0; r < 4; r++) {
                    int j = m0 + EPI_ROW(wm, mi, r);
                    int i = n0 + EPI_COL(wn, ni, r);
                    __half hv = __float2half_rn(acc[mi][ni][r]);   // = N[i][j]
                    Cm[(size_t)j * DD + i] = hv;
                    Cn[(size_t)i * DD + j] = hv;
                }
    } else {
        const int h = z - 8;
        const __half* A = g_woh + (size_t)m0 * (HH*DD) + h * DD;
        const __half* B = g_wvt + (size_t)h * DD * DD + (size_t)n0 * DD;
        gemm_h<8>(A, B, HH*DD, DD, sm, acc);
#pragma unroll
        for (int mi = 0; mi < 4; mi++)
#pragma unroll
            for (int ni = 0; ni < 8; ni++)
#pragma unroll
                for (int r = 0; r < 4; r++)
                    g_gcat[(size_t)(m0 + EPI_ROW(wm, mi, r)) * (HH*DD) + h * DD + n0 + EPI_COL(wn, ni, r)] =
                        __float2half_rn(acc[mi][ni][r]);
    }
}

// ---------------- G1_b = X_b^T X_b : grid (4,4,8) ----------------
__global__ void __launch_bounds__(128, 2) k_G1()
{
    extern __shared__ __half sm[];
    const int m0 = blockIdx.x * 128, n0 = blockIdx.y * 128, b = blockIdx.z;
    float acc[4][8][4];
    gemm_h<16>(g_xt + (size_t)b * DD * SS + (size_t)m0 * SS,
               g_xt + (size_t)b * DD * SS + (size_t)n0 * SS, SS, SS, sm, acc);

    __half* C = g_g1 + (size_t)b * DD * DD;
    const int lane = threadIdx.x & 31, warp = threadIdx.x >> 5;
    const int wm = (warp & 1) * 64, wn = (warp >> 1) * 64;
#pragma unroll
    for (int mi = 0; mi < 4; mi++)
#pragma unroll
        for (int ni = 0; ni < 8; ni++)
#pragma unroll
            for (int r = 0; r < 4; r++)
                C[(size_t)(m0 + EPI_ROW(wm, mi, r)) * DD + n0 + EPI_COL(wn, ni, r)] =
                    __float2half_rn(acc[mi][ni][r]);
}

// ---------------- FT_z[j][i] = sum_e G1_b[j][e] N_h[i][e] : grid (4,4,64) z=b*8+h ----------------
__global__ void __launch_bounds__(128, 2) k_F()
{
    extern __shared__ __half sm[];
    const int m0 = blockIdx.x * 128, n0 = blockIdx.y * 128, z = blockIdx.z;
    const int b = z >> 3, h = z & 7;
    float acc[4][8][4];
    gemm_h<8>(g_g1 + (size_t)b * DD * DD + (size_t)m0 * DD,
              g_nh + (size_t)h * DD * DD + (size_t)n0 * DD, DD, DD, sm, acc);

    __half* C = g_ft + (size_t)z * DD * DD;
    const int lane = threadIdx.x & 31, warp = threadIdx.x >> 5;
    const int wm = (warp & 1) * 64, wn = (warp >> 1) * 64;
#pragma unroll
    for (int mi = 0; mi < 4; mi++)
#pragma unroll
        for (int ni = 0; ni < 8; ni++)
#pragma unroll
            for (int r = 0; r < 4; r++)
                C[(size_t)(m0 + EPI_ROW(wm, mi, r)) * DD + n0 + EPI_COL(wn, ni, r)] =
                    __float2half_rn(acc[mi][ni][r]);
}

// ---------------- Y = X FT^T, assembled directly into Ucat : grid (8,4,64) ----------------
__global__ void __launch_bounds__(128, 2) k_Y()
{
    extern __shared__ __half sm[];
    const int m0 = blockIdx.x * 128, n0 = blockIdx.y * 128, z = blockIdx.z;
    const int b = z >> 3, h = z & 7;
    float acc[4][8][4];
    gemm_h<8>(g_xh + (size_t)b * SS * DD + (size_t)m0 * DD,
              g_ft + (size_t)z * DD * DD + (size_t)n0 * DD, DD, DD, sm, acc);

    const float invD2 = 1.0f / 262144.0f;
    const float invS  = 1.0f / (float)SS;
    const int lane = threadIdx.x & 31, warp = threadIdx.x >> 5;
    const int wm = (warp & 1) * 64, wn = (warp >> 1) * 64;
#pragma unroll
    for (int mi = 0; mi < 4; mi++)
#pragma unroll
        for (int ni = 0; ni < 8; ni++)
#pragma unroll
            for (int r = 0; r < 4; r++) {
                int s_ = m0 + EPI_ROW(wm, mi, r);
                int j  = n0 + EPI_COL(wn, ni, r);
                float rm = g_rm[z * SS + s_];
                float u = invS * (g_cs[b * DD + j] * (1.f - rm) +
                                  (acc[mi][ni][r] + g_vx[z * DD + j]) * invD2);
                g_hh[((size_t)(b * SS + s_)) * (HH*DD) + h * DD + j] = __float2half_rn(u);
            }
}

// ---------------- out = Ucat Ghat^T + chat : grid (64,4) ----------------
__global__ void __launch_bounds__(128, 2) k_out(float* __restrict__ out)
{
    extern __shared__ __half sm[];
    const int m0 = blockIdx.x * 128, n0 = blockIdx.y * 128;
    float acc[4][8][4];
    gemm_h<64>(g_hh   + (size_t)m0 * (HH*DD),
               g_gcat + (size_t)n0 * (HH*DD), HH*DD, HH*DD, sm, acc);

    const int lane = threadIdx.x & 31, warp = threadIdx.x >> 5;
    const int wm = (warp & 1) * 64, wn = (warp >> 1) * 64;
#pragma unroll
    for (int mi = 0; mi < 4; mi++)
#pragma unroll
        for (int ni = 0; ni < 8; ni++)
#pragma unroll
            for (int r = 0; r < 4; r++) {
                int row = m0 + EPI_ROW(wm, mi, r);
                int col = n0 + EPI_COL(wn, ni, r);
                out[(size_t)row * DD + col] = acc[mi][ni][r] + g_chat[col];
            }
}

// ---------------- host launcher ----------------
extern "C" void kernel_launch(void* const* d_in, const int* in_sizes, int n_in,
                              void* d_out, int out_size)
{
    const float* X  = (const float*)d_in[0];
    const float* Wq = (const float*)d_in[1];
    const float* bq = (const float*)d_in[2];
    const float* Wk = (const float*)d_in[3];
    const float* bk = (const float*)d_in[4];
    const float* Wv = (const float*)d_in[5];
    const float* bv = (const float*)d_in[6];
    const float* Wo = (const float*)d_in[7];
    const float* bo = (const float*)d_in[8];
    float* out = (float*)d_out;
    (void)bk;

    const int SMEM = 3 * STG_H * 2;   // 98304 bytes
    cudaFuncSetAttribute(k_mgemm, cudaFuncAttributeMaxDynamicSharedMemorySize, SMEM);
    cudaFuncSetAttribute(k_G1,    cudaFuncAttributeMaxDynamicSharedMemorySize, SMEM);
    cudaFuncSetAttribute(k_F,     cudaFuncAttributeMaxDynamicSharedMemorySize, SMEM);
    cudaFuncSetAttribute(k_Y,     cudaFuncAttributeMaxDynamicSharedMemorySize, SMEM);
    cudaFuncSetAttribute(k_out,   cudaFuncAttributeMaxDynamicSharedMemorySize, SMEM);

    k_cvt<<<2048, 256>>>(X, Wq, Wk, Wv, Wo);
    k_trw<<<dim3(16, 16, 24), dim3(32, 8)>>>();
    k_trx<<<dim3(16, 32, 8),  dim3(32, 8)>>>();
    k_pre1<<<dim3(8, 8), 512>>>(Wk, bq);
    k_pre2<<<8, 512>>>();
    k_chat<<<512, 256>>>(Wo, bv, bo);
    k_mgemm<<<dim3(4, 4, 16), 128, SMEM>>>();
    k_v<<<2048, 128>>>();
    k_vbar<<<64, 256>>>();
    k_colsum<<<dim3(8, 4), 128>>>();
    k_vx<<<dim3(64, 4), 128>>>();
    k_w2<<<64, 512>>>();
    k_rm<<<2048, 128>>>();
    k_G1<<<dim3(4, 4, 8), 128, SMEM>>>();
    k_F<<<dim3(4, 4, 64), 128, SMEM>>>();
    k_Y<<<dim3(8, 4, 64), 128, SMEM>>>();
    k_out<<<dim3(64, 4), 128, SMEM>>>(out);
}

// round 15
// speedup vs baseline: 4.4545x; 1.2044x over previous
#include <cuda_runtime.h>
#include <cuda_fp16.h>
#include <cstdint>

#define BB 8
#define SS 1024
#define DD 512
#define HH 8

#define STG_H (128*64*2)     // halves per stage (A 128x64 + B 128x64)

// ---------------- fp16 staged tensors ----------------
__device__ __align__(256) __half g_xh [BB*SS*DD];           // X [B,S,D]
__device__ __align__(256) __half g_xt [BB*DD*SS];           // X^T [B,D,S]
__device__ __align__(256) __half g_wqh[HH*DD*DD];
__device__ __align__(256) __half g_wkh[HH*DD*DD];
__device__ __align__(256) __half g_wvh[HH*DD*DD];
__device__ __align__(256) __half g_woh[DD*HH*DD];           // Wo [512,4096] fp16
__device__ __align__(256) __half g_wqt[HH*DD*DD];
__device__ __align__(256) __half g_wkt[HH*DD*DD];
__device__ __align__(256) __half g_wvt[HH*DD*DD];
__device__ __align__(256) __half g_nh [HH*DD*DD];           // N per head [i][j]
__device__ __align__(256) __half g_gcat[DD*HH*DD];          // Ghat [o][4096]
__device__ __align__(256) __half g_g1 [BB*DD*DD];           // G1_b = X^T X
__device__ __align__(256) __half g_ft [(size_t)BB*DD*HH*DD];// FTT_b[i][h*512+j]
__device__ __align__(256) __half g_m2 [BB*DD*DD];           // M2_b[o][i]
// fp32 small
__device__ float g_rpart[HH*8*DD];
__device__ float g_r[HH*DD], g_chat[DD];
__device__ float g_v[BB*HH*SS];
__device__ float g_vbar[BB*HH];
__device__ float g_cs[BB*DD];
__device__ float g_w2[BB*HH*DD];
__device__ float g_rm[BB*HH*SS];
__device__ float g_vx[BB*HH*DD];
__device__ float g_w1[BB*HH*DD];                             // Wv_h cs_b
__device__ float g_a [BB*HH*DD];                             // a_z[o]
__device__ float g_c2[BB*HH*DD];                             // c2_z[o]
__device__ float g_cb[BB*DD];                                // per-batch bias

// ---------------- helpers ----------------
__device__ __forceinline__ unsigned smem_u32(const void* p) {
    return (unsigned)__cvta_generic_to_shared(p);
}
__device__ __forceinline__ void cp16(void* dst, const void* src) {
    asm volatile("cp.async.cg.shared.global [%0], [%1], 16;\n"
                 :: "r"(smem_u32(dst)), "l"(src));
}

// ---------------- fp16 GEMM mainloop (validated) ----------------
template<int KT>
__device__ __forceinline__ void gemm_h(const __half* __restrict__ Ag,
                                       const __half* __restrict__ Bg,
                                       int lda, int ldb,
                                       __half* sm, float (&acc)[4][8][4])
{
    const int tid  = threadIdx.x;
    const int lane = tid & 31;
    const int warp = tid >> 5;
    const int wm = (warp & 1) * 64;
    const int wn = (warp >> 1) * 64;

#pragma unroll
    for (int mi = 0; mi < 4; mi++)
#pragma unroll
        for (int ni = 0; ni < 8; ni++)
#pragma unroll
            for (int r = 0; r < 4; r++) acc[mi][ni][r] = 0.f;

    const int srow = tid >> 3;
    const int sch  = tid & 7;

    auto stage = [&](int s, int kt) {
        __half* sA = sm + s * STG_H;
        __half* sB = sA + 128 * 64;
        const __half* ap = Ag + (size_t)srow * lda + kt * 64 + sch * 8;
        const __half* bp = Bg + (size_t)srow * ldb + kt * 64 + sch * 8;
#pragma unroll
        for (int i = 0; i < 8; i++) {
            int r = srow + i * 16;
            int sw = (sch ^ (r & 7)) * 8;
            cp16(sA + r * 64 + sw, ap + (size_t)(i * 16) * lda);
            cp16(sB + r * 64 + sw, bp + (size_t)(i * 16) * ldb);
        }
        asm volatile("cp.async.commit_group;\n");
    };

    stage(0, 0);
    stage(1, 1);

#pragma unroll 1
    for (int kt = 0; kt < KT; kt++) {
        if (kt < KT - 1) asm volatile("cp.async.wait_group 1;\n");
        else             asm volatile("cp.async.wait_group 0;\n");
        __syncthreads();

        if (kt + 2 < KT) stage((kt + 2) % 3, kt + 2);

        const __half* sA = sm + (kt % 3) * STG_H;
        const __half* sB = sA + 128 * 64;

#pragma unroll
        for (int ks = 0; ks < 4; ks++) {
            uint32_t a[4][4];
#pragma unroll
            for (int mi = 0; mi < 4; mi++) {
                int r  = wm + mi * 16 + (lane & 15);
                int ch = 2 * ks + (lane >> 4);
                unsigned ad = smem_u32(sA + r * 64 + ((ch ^ (r & 7)) * 8));
                asm volatile("ldmatrix.sync.aligned.m8n8.x4.shared.b16 {%0,%1,%2,%3}, [%4];"
                             : "=r"(a[mi][0]), "=r"(a[mi][1]), "=r"(a[mi][2]), "=r"(a[mi][3])
                             : "r"(ad));
            }
            uint32_t b[8][2];
#pragma unroll
            for (int nj = 0; nj < 4; nj++) {
                int nr = wn + nj * 16 + ((lane >> 4) << 3) + (lane & 7);
                int ch = 2 * ks + ((lane >> 3) & 1);
                unsigned ad = smem_u32(sB + nr * 64 + ((ch ^ (nr & 7)) * 8));
                uint32_t r0, r1, r2, r3;
                asm volatile("ldmatrix.sync.aligned.m8n8.x4.shared.b16 {%0,%1,%2,%3}, [%4];"
                             : "=r"(r0), "=r"(r1), "=r"(r2), "=r"(r3) : "r"(ad));
                b[nj*2][0] = r0;  b[nj*2][1] = r1;
                b[nj*2+1][0] = r2; b[nj*2+1][1] = r3;
            }
#pragma unroll
            for (int mi = 0; mi < 4; mi++)
#pragma unroll
                for (int ni = 0; ni < 8; ni++) {
                    asm volatile(
                        "mma.sync.aligned.m16n8k16.row.col.f32.f16.f16.f32 "
                        "{%0,%1,%2,%3}, {%4,%5,%6,%7}, {%8,%9}, {%0,%1,%2,%3};"
                        : "+f"(acc[mi][ni][0]), "+f"(acc[mi][ni][1]),
                          "+f"(acc[mi][ni][2]), "+f"(acc[mi][ni][3])
                        : "r"(a[mi][0]), "r"(a[mi][1]), "r"(a[mi][2]), "r"(a[mi][3]),
                          "r"(b[ni][0]), "r"(b[ni][1]));
                }
        }
    }
}

#define EPI_ROW(wm, mi, r)  ((wm) + (mi)*16 + (lane >> 2) + (((r) >> 1) << 3))
#define EPI_COL(wn, ni, r)  ((wn) + (ni)*8 + ((lane & 3) << 1) + ((r) & 1))

// ---------------- fp16 conversion ----------------
__global__ void k_cvt(const float* __restrict__ X,  const float* __restrict__ Wq,
                      const float* __restrict__ Wk, const float* __restrict__ Wv,
                      const float* __restrict__ Wo)
{
    const int stride = gridDim.x * blockDim.x;
    const int i0 = blockIdx.x * blockDim.x + threadIdx.x;
    for (int i = i0; i < BB*SS*DD; i += stride) g_xh[i]  = __float2half_rn(X[i]);
    for (int i = i0; i < HH*DD*DD; i += stride) g_wqh[i] = __float2half_rn(Wq[i]);
    for (int i = i0; i < HH*DD*DD; i += stride) g_wkh[i] = __float2half_rn(Wk[i]);
    for (int i = i0; i < HH*DD*DD; i += stride) g_wvh[i] = __float2half_rn(Wv[i]);
    for (int i = i0; i < DD*HH*DD; i += stride) g_woh[i] = __float2half_rn(Wo[i]);
}

// ---------------- transposes ----------------
__global__ void k_trw()
{
    const int m = blockIdx.z;
    const __half* src;  __half* dst;
    if (m < 8)       { src = g_wqh + (size_t)m * DD * DD;      dst = g_wqt + (size_t)m * DD * DD; }
    else if (m < 16) { src = g_wkh + (size_t)(m-8) * DD * DD;  dst = g_wkt + (size_t)(m-8) * DD * DD; }
    else             { src = g_wvh + (size_t)(m-16) * DD * DD; dst = g_wvt + (size_t)(m-16) * DD * DD; }
    __shared__ __half T[32][33];
    const int r0 = blockIdx.y * 32, c0 = blockIdx.x * 32;
    const int tx = threadIdx.x, ty = threadIdx.y;
#pragma unroll
    for (int k = 0; k < 4; k++) T[ty + 8*k][tx] = src[(size_t)(r0 + ty + 8*k) * DD + c0 + tx];
    __syncthreads();
#pragma unroll
    for (int k = 0; k < 4; k++) dst[(size_t)(c0 + ty + 8*k) * DD + r0 + tx] = T[tx][ty + 8*k];
}

__global__ void k_trx()
{
    const int b = blockIdx.z;
    const __half* src = g_xh + (size_t)b * SS * DD;
    __half* dst = g_xt + (size_t)b * DD * SS;
    __shared__ __half T[32][33];
    const int r0 = blockIdx.y * 32, c0 = blockIdx.x * 32;
    const int tx = threadIdx.x, ty = threadIdx.y;
#pragma unroll
    for (int k = 0; k < 4; k++) T[ty + 8*k][tx] = src[(size_t)(r0 + ty + 8*k) * DD + c0 + tx];
    __syncthreads();
#pragma unroll
    for (int k = 0; k < 4; k++) dst[(size_t)(c0 + ty + 8*k) * SS + r0 + tx] = T[tx][ty + 8*k];
}

// ---------------- r_h = Wk_h^T bq_h ----------------
__global__ void k_pre1(const float* __restrict__ Wk, const float* __restrict__ bq)
{
    const int h = blockIdx.x, ec = blockIdx.y, i = threadIdx.x;
    const float* wk = Wk + (size_t)h * DD * DD;
    float ra = 0.f;
    const int e0 = ec * 64;
#pragma unroll 8
    for (int e = e0; e < e0 + 64; e++)
        ra += wk[(size_t)e * DD + i] * bq[h * DD + e];
    g_rpart[(h * 8 + ec) * DD + i] = ra;
}
__global__ void k_pre2()
{
    const int h = blockIdx.x, i = threadIdx.x;
    float a = 0.f;
#pragma unroll
    for (int ec = 0; ec < 8; ec++) a += g_rpart[(h * 8 + ec) * DD + i];
    g_r[h * DD + i] = a;
}

// chat[o] = Wo[o,:].bv + bo[o]
__global__ void k_chat(const float* __restrict__ Wo, const float* __restrict__ bv,
                       const float* __restrict__ bo)
{
    const int o = blockIdx.x, t = threadIdx.x;
    float a = 0.f;
    for (int k = t; k < HH * DD; k += 256) a += Wo[(size_t)o * (HH*DD) + k] * bv[k];
    __shared__ float red[256];
    red[t] = a;
    __syncthreads();
    for (int s = 128; s > 0; s >>= 1) {
        if (t < s) red[t] += red[t + s];
        __syncthreads();
    }
    if (t == 0) g_chat[o] = red[0] + bo[o];
}

// v[z][t] = x_t . r_h
__global__ void k_v()
{
    __shared__ float sr[HH * DD];
    for (int i = threadIdx.x; i < HH * DD; i += 128) sr[i] = g_r[i];
    __syncthreads();
    const int warp = threadIdx.x >> 5, lane = threadIdx.x & 31;
    const int tok = blockIdx.x * 4 + warp;
    const int b = tok >> 10, ss = tok & 1023;
    const __half* x = g_xh + (size_t)tok * DD;
    float xv[16];
#pragma unroll
    for (int k = 0; k < 16; k++) xv[k] = __half2float(x[lane + 32 * k]);
#pragma unroll
    for (int h = 0; h < HH; h++) {
        float dv = 0.f;
#pragma unroll
        for (int k = 0; k < 16; k++) dv += xv[k] * sr[h * DD + lane + 32 * k];
#pragma unroll
        for (int o = 16; o > 0; o >>= 1) dv += __shfl_xor_sync(0xffffffffu, dv, o);
        if (lane == 0) g_v[(b * HH + h) * SS + ss] = dv;
    }
}

// vbar[z]
__global__ void k_vbar()
{
    const int z = blockIdx.x, t = threadIdx.x;
    float a = g_v[z * SS + t] + g_v[z * SS + t + 256] +
              g_v[z * SS + t + 512] + g_v[z * SS + t + 768];
    __shared__ float red[256];
    red[t] = a;
    __syncthreads();
    for (int s = 128; s > 0; s >>= 1) {
        if (t < s) red[t] += red[t + s];
        __syncthreads();
    }
    if (t == 0) g_vbar[z] = red[0] * (1.0f / SS);
}

// colsum from ORIGINAL fp32 X (main path, full precision)
__global__ void k_colsum(const float* __restrict__ X)
{
    const int b = blockIdx.x;
    const int j0 = blockIdx.y * 32;
    const int tg = threadIdx.x >> 5, jl = threadIdx.x & 31;
    const float* x = X + (size_t)b * SS * DD + j0 + jl;
    float a = 0.f;
    for (int t = tg; t < SS; t += 8) a += x[(size_t)t * DD];
    __shared__ float red[8][32];
    red[tg][jl] = a;
    __syncthreads();
    if (tg == 0) {
        float s = 0.f;
#pragma unroll
        for (int g = 0; g < 8; g++) s += red[g][jl];
        g_cs[b * DD + j0 + jl] = s;
    }
}

// vX[z][j] = sum_t v[z][t] * X[b][t][j]
__global__ void k_vx()
{
    const int z = blockIdx.x, b = z >> 3;
    const int j = blockIdx.y * 128 + threadIdx.x;
    __shared__ float sv[SS];
    for (int i = threadIdx.x; i < SS; i += 128) sv[i] = g_v[z * SS + i];
    __syncthreads();
    const __half* x = g_xh + (size_t)b * SS * DD + j;
    float a = 0.f;
    for (int t = 0; t < SS; t++) a += sv[t] * __half2float(x[(size_t)t * DD]);
    g_vx[z * DD + j] = a;
}

// w2[z][i] = N_h[i,:] . xbar_b
__global__ void k_w2()
{
    const int z = blockIdx.x, b = z >> 3, h = z & 7;
    const int i = threadIdx.x;
    __shared__ float sx[DD];
    for (int e = threadIdx.x; e < DD; e += 512) sx[e] = g_cs[b * DD + e] * (1.0f / SS);
    __syncthreads();
    const __half* nrow = g_nh + (size_t)h * DD * DD + (size_t)i * DD;
    float a = 0.f;
#pragma unroll 8
    for (int e = 0; e < DD; e++) a += __half2float(nrow[e]) * sx[e];
    g_w2[z * DD + i] = a;
}

// rm[z][s] = (x_s . w2[z] + vbar[z]) / D^2
__global__ void k_rm()
{
    const int warp = threadIdx.x >> 5, lane = threadIdx.x & 31;
    const int tok = blockIdx.x * 4 + warp;
    const int b = tok >> 10, ss = tok & 1023;
    __shared__ float sw[HH * DD];
    for (int i = threadIdx.x; i < HH * DD; i += 128) sw[i] = g_w2[(b * HH) * DD + i];
    __syncthreads();
    const __half* x = g_xh + (size_t)tok * DD;
    float xv[16];
#pragma unroll
    for (int k = 0; k < 16; k++) xv[k] = __half2float(x[lane + 32 * k]);
    const float invD2 = 1.0f / 262144.0f;
#pragma unroll
    for (int h = 0; h < HH; h++) {
        float d = 0.f;
#pragma unroll
        for (int k = 0; k < 16; k++) d += xv[k] * sw[h * DD + lane + 32 * k];
#pragma unroll
        for (int o = 16; o > 0; o >>= 1) d += __shfl_xor_sync(0xffffffffu, d, o);
        if (lane == 0)
            g_rm[(b * HH + h) * SS + ss] = (d + g_vbar[b * HH + h]) * invD2;
    }
}

// ---------------- mgemm: z<8 -> N; z>=8 -> Ghat ----------------
__global__ void __launch_bounds__(128, 2) k_mgemm()
{
    extern __shared__ __half sm[];
    const int m0 = blockIdx.x * 128, n0 = blockIdx.y * 128, z = blockIdx.z;
    float acc[4][8][4];
    const int lane = threadIdx.x & 31, warp = threadIdx.x >> 5;
    const int wm = (warp & 1) * 64, wn = (warp >> 1) * 64;

    if (z < 8) {
        const __half* A = g_wkt + (size_t)z * DD * DD + (size_t)m0 * DD;
        const __half* B = g_wqt + (size_t)z * DD * DD + (size_t)n0 * DD;
        gemm_h<8>(A, B, DD, DD, sm, acc);
        __half* Cn = g_nh + (size_t)z * DD * DD;   // [i][j] = N
#pragma unroll
        for (int mi = 0; mi < 4; mi++)
#pragma unroll
            for (int ni = 0; ni < 8; ni++)
#pragma unroll
                for (int r = 0; r < 4; r++) {
                    int j = m0 + EPI_ROW(wm, mi, r);
                    int i = n0 + EPI_COL(wn, ni, r);
                    Cn[(size_t)i * DD + j] = __float2half_rn(acc[mi][ni][r]);
                }
    } else {
        const int h = z - 8;
        const __half* A = g_woh + (size_t)m0 * (HH*DD) + h * DD;
        const __half* B = g_wvt + (size_t)h * DD * DD + (size_t)n0 * DD;
        gemm_h<8>(A, B, HH*DD, DD, sm, acc);
#pragma unroll
        for (int mi = 0; mi < 4; mi++)
#pragma unroll
            for (int ni = 0; ni < 8; ni++)
#pragma unroll
                for (int r = 0; r < 4; r++)
                    g_gcat[(size_t)(m0 + EPI_ROW(wm, mi, r)) * (HH*DD) + h * DD + n0 + EPI_COL(wn, ni, r)] =
                        __float2half_rn(acc[mi][ni][r]);
    }
}

// ---------------- G1_b = X_b^T X_b : grid (4,4,8) ----------------
__global__ void __launch_bounds__(128, 2) k_G1()
{
    extern __shared__ __half sm[];
    const int m0 = blockIdx.x * 128, n0 = blockIdx.y * 128, b = blockIdx.z;
    float acc[4][8][4];
    gemm_h<16>(g_xt + (size_t)b * DD * SS + (size_t)m0 * SS,
               g_xt + (size_t)b * DD * SS + (size_t)n0 * SS, SS, SS, sm, acc);

    __half* C = g_g1 + (size_t)b * DD * DD;
    const int lane = threadIdx.x & 31, warp = threadIdx.x >> 5;
    const int wm = (warp & 1) * 64, wn = (warp >> 1) * 64;
#pragma unroll
    for (int mi = 0; mi < 4; mi++)
#pragma unroll
        for (int ni = 0; ni < 8; ni++)
#pragma unroll
            for (int r = 0; r < 4; r++)
                C[(size_t)(m0 + EPI_ROW(wm, mi, r)) * DD + n0 + EPI_COL(wn, ni, r)] =
                    __float2half_rn(acc[mi][ni][r]);
}

// ---------------- FTT_b[i][h*512+j] = sum_e N_h[i,e] G1_b[j,e] : grid (4,4,64) ----------------
__global__ void __launch_bounds__(128, 2) k_F()
{
    extern __shared__ __half sm[];
    const int m0 = blockIdx.x * 128, n0 = blockIdx.y * 128, z = blockIdx.z;
    const int b = z >> 3, h = z & 7;
    float acc[4][8][4];
    gemm_h<8>(g_nh + (size_t)h * DD * DD + (size_t)m0 * DD,   // rows i
              g_g1 + (size_t)b * DD * DD + (size_t)n0 * DD,   // rows j (G1 symmetric)
              DD, DD, sm, acc);

    __half* C = g_ft + (size_t)b * DD * (HH*DD);
    const int lane = threadIdx.x & 31, warp = threadIdx.x >> 5;
    const int wm = (warp & 1) * 64, wn = (warp >> 1) * 64;
#pragma unroll
    for (int mi = 0; mi < 4; mi++)
#pragma unroll
        for (int ni = 0; ni < 8; ni++)
#pragma unroll
            for (int r = 0; r < 4; r++) {
                int i = m0 + EPI_ROW(wm, mi, r);
                int j = n0 + EPI_COL(wn, ni, r);
                C[(size_t)i * (HH*DD) + h * DD + j] = __float2half_rn(acc[mi][ni][r]);
            }
}

// ---------------- w1[z][e] = sum_j Wv_h[e,j] cs_b[j] (fp32) ----------------
__global__ void k_w1(const float* __restrict__ Wv)
{
    const int z = blockIdx.x, b = z >> 3, h = z & 7;
    const int warp = threadIdx.x >> 5, lane = threadIdx.x & 31;
    __shared__ float scs[DD];
    for (int i = threadIdx.x; i < DD; i += 256) scs[i] = g_cs[b * DD + i];
    __syncthreads();
    const int e = blockIdx.y * 8 + warp;
    const float* wrow = Wv + (size_t)h * DD * DD + (size_t)e * DD;
    float a = 0.f;
#pragma unroll
    for (int k = 0; k < 16; k++) a += wrow[lane + 32 * k] * scs[lane + 32 * k];
#pragma unroll
    for (int o = 16; o > 0; o >>= 1) a += __shfl_xor_sync(0xffffffffu, a, o);
    if (lane == 0) g_w1[z * DD + e] = a;
}

// ---------------- a_z[o] = Wo[o, hD:].w1_z (fp32); c2_z[o] = vx_z . Ghat_h[o,:] ----------------
__global__ void k_ac2(const float* __restrict__ Wo)
{
    const int z = blockIdx.x, h = z & 7;
    const int warp = threadIdx.x >> 5, lane = threadIdx.x & 31;
    __shared__ float sw[DD], sv[DD];
    for (int i = threadIdx.x; i < DD; i += 256) {
        sw[i] = g_w1[z * DD + i];
        sv[i] = g_vx[z * DD + i];
    }
    __syncthreads();
    const int o = blockIdx.y * 8 + warp;
    const float*  worow = Wo + (size_t)o * (HH*DD) + h * DD;
    const __half* grow  = g_gcat + (size_t)o * (HH*DD) + h * DD;
    float a = 0.f, c = 0.f;
#pragma unroll
    for (int k = 0; k < 16; k++) {
        int j = lane + 32 * k;
        a += worow[j] * sw[j];
        c += __half2float(grow[j]) * sv[j];
    }
#pragma unroll
    for (int off = 16; off > 0; off >>= 1) {
        a += __shfl_xor_sync(0xffffffffu, a, off);
        c += __shfl_xor_sync(0xffffffffu, c, off);
    }
    if (lane == 0) { g_a[z * DD + o] = a; g_c2[z * DD + o] = c; }
}

// ---------------- cb_b[o] = invS*sum_h a + invS*invD2*sum_h c2 + chat ----------------
__global__ void k_cb()
{
    const int b = blockIdx.x;
    const int o = blockIdx.y * 128 + threadIdx.x;
    float sa = 0.f, sc = 0.f;
#pragma unroll
    for (int h = 0; h < HH; h++) {
        sa += g_a [(b * HH + h) * DD + o];
        sc += g_c2[(b * HH + h) * DD + o];
    }
    const float invS = 1.0f / SS, invD2 = 1.0f / 262144.0f;
    g_cb[b * DD + o] = invS * (sa + sc * invD2) + g_chat[o];
}

// ---------------- M2_b[o][i] = sum_{h,j} Ghat[o,hj] FTT_b[i,hj] : grid (4,4,8) ----------------
__global__ void __launch_bounds__(128, 2) k_M()
{
    extern __shared__ __half sm[];
    const int m0 = blockIdx.x * 128, n0 = blockIdx.y * 128, b = blockIdx.z;
    float acc[4][8][4];
    gemm_h<64>(g_gcat + (size_t)m0 * (HH*DD),                       // rows o
               g_ft + (size_t)b * DD * (HH*DD) + (size_t)n0 * (HH*DD), // rows i
               HH*DD, HH*DD, sm, acc);

    __half* C = g_m2 + (size_t)b * DD * DD;
    const int lane = threadIdx.x & 31, warp = threadIdx.x >> 5;
    const int wm = (warp & 1) * 64, wn = (warp >> 1) * 64;
#pragma unroll
    for (int mi = 0; mi < 4; mi++)
#pragma unroll
        for (int ni = 0; ni < 8; ni++)
#pragma unroll
            for (int r = 0; r < 4; r++)
                C[(size_t)(m0 + EPI_ROW(wm, mi, r)) * DD + n0 + EPI_COL(wn, ni, r)] =
                    __float2half_rn(acc[mi][ni][r]);
}

// ---------------- out = invS*invD2*(X M2^T) + cb - invS*sum_h rm*a : grid (64,4) ----------------
__global__ void __launch_bounds__(128, 2) k_out2(float* __restrict__ out)
{
    extern __shared__ __half sm[];
    const int m0 = blockIdx.x * 128, n0 = blockIdx.y * 128;
    const int b = m0 >> 10;
    float acc[4][8][4];
    gemm_h<8>(g_xh + (size_t)m0 * DD,
              g_m2 + (size_t)b * DD * DD + (size_t)n0 * DD, DD, DD, sm, acc);

    // reuse dynamic smem for fp32 epilogue data
    __syncthreads();
    float* sA  = (float*)sm;          // [8][128] a_z slice (cols n0..n0+127)
    float* srm = sA + 8 * 128;        // [8][128] rm rows (m0..m0+127)
    const int s0 = m0 & 1023;
    for (int i = threadIdx.x; i < 8 * 128; i += 128) {
        int h = i >> 7, l = i & 127;
        sA [i] = g_a [(b * HH + h) * DD + n0 + l];
        srm[i] = g_rm[(b * HH + h) * SS + s0 + l];
    }
    __syncthreads();

    const float invS = 1.0f / SS, invD2 = 1.0f / 262144.0f;
    const int lane = threadIdx.x & 31, warp = threadIdx.x >> 5;
    const int wm = (warp & 1) * 64, wn = (warp >> 1) * 64;
#pragma unroll
    for (int mi = 0; mi < 4; mi++)
#pragma unroll
        for (int ni = 0; ni < 8; ni++)
#pragma unroll
            for (int r = 0; r < 4; r++) {
                int rl = EPI_ROW(wm, mi, r);        // 0..127 local
                int cl = EPI_COL(wn, ni, r);        // 0..127 local
                float corr = 0.f;
#pragma unroll
                for (int h = 0; h < HH; h++) corr += srm[h * 128 + rl] * sA[h * 128 + cl];
                out[(size_t)(m0 + rl) * DD + n0 + cl] =
                    acc[mi][ni][r] * invS * invD2 + g_cb[b * DD + n0 + cl] - invS * corr;
            }
}

// ---------------- host launcher ----------------
extern "C" void kernel_launch(void* const* d_in, const int* in_sizes, int n_in,
                              void* d_out, int out_size)
{
    const float* X  = (const float*)d_in[0];
    const float* Wq = (const float*)d_in[1];
    const float* bq = (const float*)d_in[2];
    const float* Wk = (const float*)d_in[3];
    const float* bk = (const float*)d_in[4];
    const float* Wv = (const float*)d_in[5];
    const float* bv = (const float*)d_in[6];
    const float* Wo = (const float*)d_in[7];
    const float* bo = (const float*)d_in[8];
    float* out = (float*)d_out;
    (void)bk;

    const int SMEM = 3 * STG_H * 2;   // 98304 bytes
    cudaFuncSetAttribute(k_mgemm, cudaFuncAttributeMaxDynamicSharedMemorySize, SMEM);
    cudaFuncSetAttribute(k_G1,    cudaFuncAttributeMaxDynamicSharedMemorySize, SMEM);
    cudaFuncSetAttribute(k_F,     cudaFuncAttributeMaxDynamicSharedMemorySize, SMEM);
    cudaFuncSetAttribute(k_M,     cudaFuncAttributeMaxDynamicSharedMemorySize, SMEM);
    cudaFuncSetAttribute(k_out2,  cudaFuncAttributeMaxDynamicSharedMemorySize, SMEM);

    k_cvt<<<2048, 256>>>(X, Wq, Wk, Wv, Wo);
    k_trw<<<dim3(16, 16, 24), dim3(32, 8)>>>();
    k_trx<<<dim3(16, 32, 8),  dim3(32, 8)>>>();
    k_pre1<<<dim3(8, 8), 512>>>(Wk, bq);
    k_pre2<<<8, 512>>>();
    k_chat<<<512, 256>>>(Wo, bv, bo);
    k_mgemm<<<dim3(4, 4, 16), 128, SMEM>>>();
    k_v<<<2048, 128>>>();
    k_vbar<<<64, 256>>>();
    k_colsum<<<dim3(8, 16), 256>>>(X);
    k_vx<<<dim3(64, 4), 128>>>();
    k_w2<<<64, 512>>>();
    k_rm<<<2048, 128>>>();
    k_G1<<<dim3(4, 4, 8), 128, SMEM>>>();
    k_F<<<dim3(4, 4, 64), 128, SMEM>>>();
    k_w1<<<dim3(64, 64), 256>>>(Wv);
    k_ac2<<<dim3(64, 64), 256>>>(Wo);
    k_cb<<<dim3(8, 4), 128>>>();
    k_M<<<dim3(4, 4, 8), 128, SMEM>>>();
    k_out2<<<dim3(64, 4), 128, SMEM>>>(out);
}

// round 16
// speedup vs baseline: 6.8419x; 1.5359x over previous
#include <cuda_runtime.h>
#include <cuda_fp16.h>
#include <cstdint>

#define BB 8
#define SS 1024
#define DD 512
#define HH 8

#define STG_H (128*64*2)     // halves per stage (A 128x64 + B 128x64)

// ---------------- fp16 staged tensors ----------------
__device__ __align__(256) __half g_xh [BB*SS*DD];           // X [B,S,D]
__device__ __align__(256) __half g_xt [BB*DD*SS];           // X^T [B,D,S]
__device__ __align__(256) __half g_woh[DD*HH*DD];           // Wo [512,4096] fp16
__device__ __align__(256) __half g_wqt[HH*DD*DD];           // Wq^T per head [i][e]
__device__ __align__(256) __half g_wkt[HH*DD*DD];
__device__ __align__(256) __half g_wvt[HH*DD*DD];
__device__ __align__(256) __half g_nh [HH*DD*DD];           // N per head [i][j]
__device__ __align__(256) __half g_gcat[DD*HH*DD];          // Ghat [o][4096]
__device__ __align__(256) __half g_g1 [BB*DD*DD];           // G1_b = X^T X
__device__ __align__(256) __half g_ft [(size_t)BB*DD*HH*DD];// FTT_b[i][h*512+j]
__device__ __align__(256) __half g_m2 [BB*DD*DD];           // M2_b[o][i]
// fp32 small
__device__ float g_r[HH*DD], g_chat[DD];
__device__ float g_vbar[BB*HH];
__device__ float g_cs[BB*DD];
__device__ float g_w2[BB*HH*DD];
__device__ float g_rm[BB*HH*SS];
__device__ float g_vx[BB*HH*DD];
__device__ float g_w1[BB*HH*DD];
__device__ float g_a [BB*HH*DD];
__device__ float g_c2[BB*HH*DD];
__device__ float g_cb[BB*DD];

// ---------------- helpers ----------------
__device__ __forceinline__ unsigned smem_u32(const void* p) {
    return (unsigned)__cvta_generic_to_shared(p);
}
__device__ __forceinline__ void cp16(void* dst, const void* src) {
    asm volatile("cp.async.cg.shared.global [%0], [%1], 16;\n"
                 :: "r"(smem_u32(dst)), "l"(src));
}

// ---------------- fp16 GEMM mainloop (validated, unchanged) ----------------
template<int KT>
__device__ __forceinline__ void gemm_h(const __half* __restrict__ Ag,
                                       const __half* __restrict__ Bg,
                                       int lda, int ldb,
                                       __half* sm, float (&acc)[4][8][4])
{
    const int tid  = threadIdx.x;
    const int lane = tid & 31;
    const int warp = tid >> 5;
    const int wm = (warp & 1) * 64;
    const int wn = (warp >> 1) * 64;

#pragma unroll
    for (int mi = 0; mi < 4; mi++)
#pragma unroll
        for (int ni = 0; ni < 8; ni++)
#pragma unroll
            for (int r = 0; r < 4; r++) acc[mi][ni][r] = 0.f;

    const int srow = tid >> 3;
    const int sch  = tid & 7;

    auto stage = [&](int s, int kt) {
        __half* sA = sm + s * STG_H;
        __half* sB = sA + 128 * 64;
        const __half* ap = Ag + (size_t)srow * lda + kt * 64 + sch * 8;
        const __half* bp = Bg + (size_t)srow * ldb + kt * 64 + sch * 8;
#pragma unroll
        for (int i = 0; i < 8; i++) {
            int r = srow + i * 16;
            int sw = (sch ^ (r & 7)) * 8;
            cp16(sA + r * 64 + sw, ap + (size_t)(i * 16) * lda);
            cp16(sB + r * 64 + sw, bp + (size_t)(i * 16) * ldb);
        }
        asm volatile("cp.async.commit_group;\n");
    };

    stage(0, 0);
    stage(1, 1);

#pragma unroll 1
    for (int kt = 0; kt < KT; kt++) {
        if (kt < KT - 1) asm volatile("cp.async.wait_group 1;\n");
        else             asm volatile("cp.async.wait_group 0;\n");
        __syncthreads();

        if (kt + 2 < KT) stage((kt + 2) % 3, kt + 2);

        const __half* sA = sm + (kt % 3) * STG_H;
        const __half* sB = sA + 128 * 64;

#pragma unroll
        for (int ks = 0; ks < 4; ks++) {
            uint32_t a[4][4];
#pragma unroll
            for (int mi = 0; mi < 4; mi++) {
                int r  = wm + mi * 16 + (lane & 15);
                int ch = 2 * ks + (lane >> 4);
                unsigned ad = smem_u32(sA + r * 64 + ((ch ^ (r & 7)) * 8));
                asm volatile("ldmatrix.sync.aligned.m8n8.x4.shared.b16 {%0,%1,%2,%3}, [%4];"
                             : "=r"(a[mi][0]), "=r"(a[mi][1]), "=r"(a[mi][2]), "=r"(a[mi][3])
                             : "r"(ad));
            }
            uint32_t b[8][2];
#pragma unroll
            for (int nj = 0; nj < 4; nj++) {
                int nr = wn + nj * 16 + ((lane >> 4) << 3) + (lane & 7);
                int ch = 2 * ks + ((lane >> 3) & 1);
                unsigned ad = smem_u32(sB + nr * 64 + ((ch ^ (nr & 7)) * 8));
                uint32_t r0, r1, r2, r3;
                asm volatile("ldmatrix.sync.aligned.m8n8.x4.shared.b16 {%0,%1,%2,%3}, [%4];"
                             : "=r"(r0), "=r"(r1), "=r"(r2), "=r"(r3) : "r"(ad));
                b[nj*2][0] = r0;  b[nj*2][1] = r1;
                b[nj*2+1][0] = r2; b[nj*2+1][1] = r3;
            }
#pragma unroll
            for (int mi = 0; mi < 4; mi++)
#pragma unroll
                for (int ni = 0; ni < 8; ni++) {
                    asm volatile(
                        "mma.sync.aligned.m16n8k16.row.col.f32.f16.f16.f32 "
                        "{%0,%1,%2,%3}, {%4,%5,%6,%7}, {%8,%9}, {%0,%1,%2,%3};"
                        : "+f"(acc[mi][ni][0]), "+f"(acc[mi][ni][1]),
                          "+f"(acc[mi][ni][2]), "+f"(acc[mi][ni][3])
                        : "r"(a[mi][0]), "r"(a[mi][1]), "r"(a[mi][2]), "r"(a[mi][3]),
                          "r"(b[ni][0]), "r"(b[ni][1]));
                }
        }
    }
}

#define EPI_ROW(wm, mi, r)  ((wm) + (mi)*16 + (lane >> 2) + (((r) >> 1) << 3))
#define EPI_COL(wn, ni, r)  ((wn) + (ni)*8 + ((lane & 3) << 1) + ((r) & 1))

// ---------------- fp16 conversion (X and Wo only) ----------------
__global__ void k_cvt(const float* __restrict__ X, const float* __restrict__ Wo)
{
    const int stride = gridDim.x * blockDim.x;
    const int i0 = blockIdx.x * blockDim.x + threadIdx.x;
    for (int i = i0; i < BB*SS*DD; i += stride) g_xh[i]  = __float2half_rn(X[i]);
    for (int i = i0; i < DD*HH*DD; i += stride) g_woh[i] = __float2half_rn(Wo[i]);
}

// ---------------- weight transposes: fp32 source -> fp16 transposed ----------------
__global__ void k_trw(const float* __restrict__ Wq, const float* __restrict__ Wk,
                      const float* __restrict__ Wv)
{
    const int m = blockIdx.z;
    const float* src;  __half* dst;
    if (m < 8)       { src = Wq + (size_t)m * DD * DD;      dst = g_wqt + (size_t)m * DD * DD; }
    else if (m < 16) { src = Wk + (size_t)(m-8) * DD * DD;  dst = g_wkt + (size_t)(m-8) * DD * DD; }
    else             { src = Wv + (size_t)(m-16) * DD * DD; dst = g_wvt + (size_t)(m-16) * DD * DD; }
    __shared__ __half T[32][33];
    const int r0 = blockIdx.y * 32, c0 = blockIdx.x * 32;
    const int tx = threadIdx.x, ty = threadIdx.y;
#pragma unroll
    for (int k = 0; k < 4; k++)
        T[ty + 8*k][tx] = __float2half_rn(src[(size_t)(r0 + ty + 8*k) * DD + c0 + tx]);
    __syncthreads();
#pragma unroll
    for (int k = 0; k < 4; k++) dst[(size_t)(c0 + ty + 8*k) * DD + r0 + tx] = T[tx][ty + 8*k];
}

__global__ void k_trx()
{
    const int b = blockIdx.z;
    const __half* src = g_xh + (size_t)b * SS * DD;
    __half* dst = g_xt + (size_t)b * DD * SS;
    __shared__ __half T[32][33];
    const int r0 = blockIdx.y * 32, c0 = blockIdx.x * 32;
    const int tx = threadIdx.x, ty = threadIdx.y;
#pragma unroll
    for (int k = 0; k < 4; k++) T[ty + 8*k][tx] = src[(size_t)(r0 + ty + 8*k) * DD + c0 + tx];
    __syncthreads();
#pragma unroll
    for (int k = 0; k < 4; k++) dst[(size_t)(c0 + ty + 8*k) * SS + r0 + tx] = T[tx][ty + 8*k];
}

// ---------------- r_h[i] = wkt_h[i,:].bq_h (fp16 weights; correction-only) ----------------
// grid (8, 64), block 256: warp -> one i
__global__ void k_r(const float* __restrict__ bq)
{
    const int h = blockIdx.x;
    const int warp = threadIdx.x >> 5, lane = threadIdx.x & 31;
    __shared__ float sb[DD];
    for (int i = threadIdx.x; i < DD; i += 256) sb[i] = bq[h * DD + i];
    __syncthreads();
    const int i = blockIdx.y * 8 + warp;
    const __half* row = g_wkt + (size_t)h * DD * DD + (size_t)i * DD;
    float a = 0.f;
#pragma unroll
    for (int k = 0; k < 16; k++) a += __half2float(row[lane + 32 * k]) * sb[lane + 32 * k];
#pragma unroll
    for (int o = 16; o > 0; o >>= 1) a += __shfl_xor_sync(0xffffffffu, a, o);
    if (lane == 0) g_r[h * DD + i] = a;
}

// chat[o] = Wo[o,:].bv + bo[o]
__global__ void k_chat(const float* __restrict__ Wo, const float* __restrict__ bv,
                       const float* __restrict__ bo)
{
    const int o = blockIdx.x, t = threadIdx.x;
    float a = 0.f;
    for (int k = t; k < HH * DD; k += 256) a += Wo[(size_t)o * (HH*DD) + k] * bv[k];
    __shared__ float red[256];
    red[t] = a;
    __syncthreads();
    for (int s = 128; s > 0; s >>= 1) {
        if (t < s) red[t] += red[t + s];
        __syncthreads();
    }
    if (t == 0) g_chat[o] = red[0] + bo[o];
}

// colsum from ORIGINAL fp32 X
__global__ void k_colsum(const float* __restrict__ X)
{
    const int b = blockIdx.x;
    const int j0 = blockIdx.y * 32;
    const int tg = threadIdx.x >> 5, jl = threadIdx.x & 31;
    const float* x = X + (size_t)b * SS * DD + j0 + jl;
    float a = 0.f;
    for (int t = tg; t < SS; t += 8) a += x[(size_t)t * DD];
    __shared__ float red[8][32];
    red[tg][jl] = a;
    __syncthreads();
    if (tg == 0) {
        float s = 0.f;
#pragma unroll
        for (int g = 0; g < 8; g++) s += red[g][jl];
        g_cs[b * DD + j0 + jl] = s;
    }
}

// vbar[z] = xbar_b . r_h  (64 tiny dots; one warp each)
__global__ void k_vbar()
{
    const int z = blockIdx.x, b = z >> 3, h = z & 7;
    const int lane = threadIdx.x;
    const float invS = 1.0f / SS;
    float a = 0.f;
#pragma unroll
    for (int k = 0; k < 16; k++) {
        int e = lane + 32 * k;
        a += g_cs[b * DD + e] * g_r[h * DD + e];
    }
#pragma unroll
    for (int o = 16; o > 0; o >>= 1) a += __shfl_xor_sync(0xffffffffu, a, o);
    if (lane == 0) g_vbar[z] = a * invS;
}

// w1: weights-outer — read Wv row once, dot with 8 batch cs vectors
// grid (8 h, 64), block 256: warp -> e = blockIdx.y*8+warp
__global__ void k_w1(const float* __restrict__ Wv)
{
    const int h = blockIdx.x;
    const int warp = threadIdx.x >> 5, lane = threadIdx.x & 31;
    __shared__ float scs[BB][DD];
    for (int i = threadIdx.x; i < BB * DD; i += 256) scs[i >> 9][i & 511] = g_cs[i];
    __syncthreads();
    const int e = blockIdx.y * 8 + warp;
    const float* wrow = Wv + (size_t)h * DD * DD + (size_t)e * DD;
    float wv[16];
#pragma unroll
    for (int k = 0; k < 16; k++) wv[k] = wrow[lane + 32 * k];
#pragma unroll
    for (int b = 0; b < BB; b++) {
        float a = 0.f;
#pragma unroll
        for (int k = 0; k < 16; k++) a += wv[k] * scs[b][lane + 32 * k];
#pragma unroll
        for (int o = 16; o > 0; o >>= 1) a += __shfl_xor_sync(0xffffffffu, a, o);
        if (lane == 0) g_w1[(b * HH + h) * DD + e] = a;
    }
}

// w2[z][i] = N_h[i,:] . xbar_b  (weights-outer over 8 batches)
__global__ void k_w2()
{
    const int h = blockIdx.x;
    const int warp = threadIdx.x >> 5, lane = threadIdx.x & 31;
    __shared__ float sx[BB][DD];
    const float invS = 1.0f / SS;
    for (int i = threadIdx.x; i < BB * DD; i += 256) sx[i >> 9][i & 511] = g_cs[i] * invS;
    __syncthreads();
    const int i = blockIdx.y * 8 + warp;
    const __half* nrow = g_nh + (size_t)h * DD * DD + (size_t)i * DD;
    float nv[16];
#pragma unroll
    for (int k = 0; k < 16; k++) nv[k] = __half2float(nrow[lane + 32 * k]);
#pragma unroll
    for (int b = 0; b < BB; b++) {
        float a = 0.f;
#pragma unroll
        for (int k = 0; k < 16; k++) a += nv[k] * sx[b][lane + 32 * k];
#pragma unroll
        for (int o = 16; o > 0; o >>= 1) a += __shfl_xor_sync(0xffffffffu, a, o);
        if (lane == 0) g_w2[(b * HH + h) * DD + i] = a;
    }
}

// vx[z][j] = (G1_b r_h)[j]  (G1 row read once, dotted with 8 head r vectors)
// grid (8 b, 64), block 256: warp -> j
__global__ void k_vx()
{
    const int b = blockIdx.x;
    const int warp = threadIdx.x >> 5, lane = threadIdx.x & 31;
    __shared__ float sr[HH][DD];
    for (int i = threadIdx.x; i < HH * DD; i += 256) sr[i >> 9][i & 511] = g_r[i];
    __syncthreads();
    const int j = blockIdx.y * 8 + warp;
    const __half* grow = g_g1 + (size_t)b * DD * DD + (size_t)j * DD;
    float gv[16];
#pragma unroll
    for (int k = 0; k < 16; k++) gv[k] = __half2float(grow[lane + 32 * k]);
#pragma unroll
    for (int h = 0; h < HH; h++) {
        float a = 0.f;
#pragma unroll
        for (int k = 0; k < 16; k++) a += gv[k] * sr[h][lane + 32 * k];
#pragma unroll
        for (int o = 16; o > 0; o >>= 1) a += __shfl_xor_sync(0xffffffffu, a, o);
        if (lane == 0) g_vx[(b * HH + h) * DD + j] = a;
    }
}

// rm[z][s] = (x_s . w2[z] + vbar[z]) / D^2
__global__ void k_rm()
{
    const int warp = threadIdx.x >> 5, lane = threadIdx.x & 31;
    const int tok = blockIdx.x * 4 + warp;
    const int b = tok >> 10, ss = tok & 1023;
    __shared__ float sw[HH * DD];
    for (int i = threadIdx.x; i < HH * DD; i += 128) sw[i] = g_w2[(b * HH) * DD + i];
    __syncthreads();
    const __half* x = g_xh + (size_t)tok * DD;
    float xv[16];
#pragma unroll
    for (int k = 0; k < 16; k++) xv[k] = __half2float(x[lane + 32 * k]);
    const float invD2 = 1.0f / 262144.0f;
#pragma unroll
    for (int h = 0; h < HH; h++) {
        float d = 0.f;
#pragma unroll
        for (int k = 0; k < 16; k++) d += xv[k] * sw[h * DD + lane + 32 * k];
#pragma unroll
        for (int o = 16; o > 0; o >>= 1) d += __shfl_xor_sync(0xffffffffu, d, o);
        if (lane == 0)
            g_rm[(b * HH + h) * SS + ss] = (d + g_vbar[b * HH + h]) * invD2;
    }
}

// ---------------- mgemm: z<8 -> N; z>=8 -> Ghat ----------------
__global__ void __launch_bounds__(128, 2) k_mgemm()
{
    extern __shared__ __half sm[];
    const int m0 = blockIdx.x * 128, n0 = blockIdx.y * 128, z = blockIdx.z;
    float acc[4][8][4];
    const int lane = threadIdx.x & 31, warp = threadIdx.x >> 5;
    const int wm = (warp & 1) * 64, wn = (warp >> 1) * 64;

    if (z < 8) {
        const __half* A = g_wkt + (size_t)z * DD * DD + (size_t)m0 * DD;
        const __half* B = g_wqt + (size_t)z * DD * DD + (size_t)n0 * DD;
        gemm_h<8>(A, B, DD, DD, sm, acc);
        __half* Cn = g_nh + (size_t)z * DD * DD;
#pragma unroll
        for (int mi = 0; mi < 4; mi++)
#pragma unroll
            for (int ni = 0; ni < 8; ni++)
#pragma unroll
                for (int r = 0; r < 4; r++) {
                    int j = m0 + EPI_ROW(wm, mi, r);
                    int i = n0 + EPI_COL(wn, ni, r);
                    Cn[(size_t)i * DD + j] = __float2half_rn(acc[mi][ni][r]);
                }
    } else {
        const int h = z - 8;
        const __half* A = g_woh + (size_t)m0 * (HH*DD) + h * DD;
        const __half* B = g_wvt + (size_t)h * DD * DD + (size_t)n0 * DD;
        gemm_h<8>(A, B, HH*DD, DD, sm, acc);
#pragma unroll
        for (int mi = 0; mi < 4; mi++)
#pragma unroll
            for (int ni = 0; ni < 8; ni++)
#pragma unroll
                for (int r = 0; r < 4; r++)
                    g_gcat[(size_t)(m0 + EPI_ROW(wm, mi, r)) * (HH*DD) + h * DD + n0 + EPI_COL(wn, ni, r)] =
                        __float2half_rn(acc[mi][ni][r]);
    }
}

// ---------------- G1_b = X_b^T X_b ----------------
__global__ void __launch_bounds__(128, 2) k_G1()
{
    extern __shared__ __half sm[];
    const int m0 = blockIdx.x * 128, n0 = blockIdx.y * 128, b = blockIdx.z;
    float acc[4][8][4];
    gemm_h<16>(g_xt + (size_t)b * DD * SS + (size_t)m0 * SS,
               g_xt + (size_t)b * DD * SS + (size_t)n0 * SS, SS, SS, sm, acc);

    __half* C = g_g1 + (size_t)b * DD * DD;
    const int lane = threadIdx.x & 31, warp = threadIdx.x >> 5;
    const int wm = (warp & 1) * 64, wn = (warp >> 1) * 64;
#pragma unroll
    for (int mi = 0; mi < 4; mi++)
#pragma unroll
        for (int ni = 0; ni < 8; ni++)
#pragma unroll
            for (int r = 0; r < 4; r++)
                C[(size_t)(m0 + EPI_ROW(wm, mi, r)) * DD + n0 + EPI_COL(wn, ni, r)] =
                    __float2half_rn(acc[mi][ni][r]);
}

// ---------------- FTT_b[i][h*512+j] = sum_e N_h[i,e] G1_b[j,e] ----------------
__global__ void __launch_bounds__(128, 2) k_F()
{
    extern __shared__ __half sm[];
    const int m0 = blockIdx.x * 128, n0 = blockIdx.y * 128, z = blockIdx.z;
    const int b = z >> 3, h = z & 7;
    float acc[4][8][4];
    gemm_h<8>(g_nh + (size_t)h * DD * DD + (size_t)m0 * DD,
              g_g1 + (size_t)b * DD * DD + (size_t)n0 * DD,
              DD, DD, sm, acc);

    __half* C = g_ft + (size_t)b * DD * (HH*DD);
    const int lane = threadIdx.x & 31, warp = threadIdx.x >> 5;
    const int wm = (warp & 1) * 64, wn = (warp >> 1) * 64;
#pragma unroll
    for (int mi = 0; mi < 4; mi++)
#pragma unroll
        for (int ni = 0; ni < 8; ni++)
#pragma unroll
            for (int r = 0; r < 4; r++) {
                int i = m0 + EPI_ROW(wm, mi, r);
                int j = n0 + EPI_COL(wn, ni, r);
                C[(size_t)i * (HH*DD) + h * DD + j] = __float2half_rn(acc[mi][ni][r]);
            }
}

// ---------------- a/c2: weights-outer over 8 batches ----------------
// grid (8 h, 64 oc), block 256: warp -> o = oc*8+warp
__global__ void k_ac2(const float* __restrict__ Wo)
{
    const int h = blockIdx.x;
    const int warp = threadIdx.x >> 5, lane = threadIdx.x & 31;
    __shared__ float sw1[BB][DD];
    __shared__ float svx[BB][DD];
    for (int i = threadIdx.x; i < BB * DD; i += 256) {
        int b = i >> 9, e = i & 511;
        sw1[b][e] = g_w1[(b * HH + h) * DD + e];
        svx[b][e] = g_vx[(b * HH + h) * DD + e];
    }
    __syncthreads();
    const int o = blockIdx.y * 8 + warp;
    const float*  worow = Wo + (size_t)o * (HH*DD) + h * DD;
    const __half* grow  = g_gcat + (size_t)o * (HH*DD) + h * DD;
    float wv[16], gv[16];
#pragma unroll
    for (int k = 0; k < 16; k++) {
        wv[k] = worow[lane + 32 * k];
        gv[k] = __half2float(grow[lane + 32 * k]);
    }
#pragma unroll
    for (int b = 0; b < BB; b++) {
        float a = 0.f, c = 0.f;
#pragma unroll
        for (int k = 0; k < 16; k++) {
            a += wv[k] * sw1[b][lane + 32 * k];
            c += gv[k] * svx[b][lane + 32 * k];
        }
#pragma unroll
        for (int off = 16; off > 0; off >>= 1) {
            a += __shfl_xor_sync(0xffffffffu, a, off);
            c += __shfl_xor_sync(0xffffffffu, c, off);
        }
        if (lane == 0) {
            g_a [(b * HH + h) * DD + o] = a;
            g_c2[(b * HH + h) * DD + o] = c;
        }
    }
}

// cb_b[o] = invS*(sum_h a + invD2*sum_h c2) + chat
__global__ void k_cb()
{
    const int b = blockIdx.x;
    const int o = blockIdx.y * 128 + threadIdx.x;
    float sa = 0.f, sc = 0.f;
#pragma unroll
    for (int h = 0; h < HH; h++) {
        sa += g_a [(b * HH + h) * DD + o];
        sc += g_c2[(b * HH + h) * DD + o];
    }
    const float invS = 1.0f / SS, invD2 = 1.0f / 262144.0f;
    g_cb[b * DD + o] = invS * (sa + sc * invD2) + g_chat[o];
}

// ---------------- M2_b[o][i] = sum_{h,j} Ghat[o,hj] FTT_b[i,hj] ----------------
__global__ void __launch_bounds__(128, 2) k_M()
{
    extern __shared__ __half sm[];
    const int m0 = blockIdx.x * 128, n0 = blockIdx.y * 128, b = blockIdx.z;
    float acc[4][8][4];
    gemm_h<64>(g_gcat + (size_t)m0 * (HH*DD),
               g_ft + (size_t)b * DD * (HH*DD) + (size_t)n0 * (HH*DD),
               HH*DD, HH*DD, sm, acc);

    __half* C = g_m2 + (size_t)b * DD * DD;
    const int lane = threadIdx.x & 31, warp = threadIdx.x >> 5;
    const int wm = (warp & 1) * 64, wn = (warp >> 1) * 64;
#pragma unroll
    for (int mi = 0; mi < 4; mi++)
#pragma unroll
        for (int ni = 0; ni < 8; ni++)
#pragma unroll
            for (int r = 0; r < 4; r++)
                C[(size_t)(m0 + EPI_ROW(wm, mi, r)) * DD + n0 + EPI_COL(wn, ni, r)] =
                    __float2half_rn(acc[mi][ni][r]);
}

// ---------------- out = invS*invD2*(X M2^T) + cb - invS*sum_h rm*a ----------------
__global__ void __launch_bounds__(128, 2) k_out2(float* __restrict__ out)
{
    extern __shared__ __half sm[];
    const int m0 = blockIdx.x * 128, n0 = blockIdx.y * 128;
    const int b = m0 >> 10;
    float acc[4][8][4];
    gemm_h<8>(g_xh + (size_t)m0 * DD,
              g_m2 + (size_t)b * DD * DD + (size_t)n0 * DD, DD, DD, sm, acc);

    __syncthreads();
    float* sA  = (float*)sm;          // [8][128] a slice
    float* srm = sA + 8 * 128;        // [8][128] rm rows
    const int s0 = m0 & 1023;
    for (int i = threadIdx.x; i < 8 * 128; i += 128) {
        int h = i >> 7, l = i & 127;
        sA [i] = g_a [(b * HH + h) * DD + n0 + l];
        srm[i] = g_rm[(b * HH + h) * SS + s0 + l];
    }
    __syncthreads();

    const float invS = 1.0f / SS, invD2 = 1.0f / 262144.0f;
    const int lane = threadIdx.x & 31, warp = threadIdx.x >> 5;
    const int wm = (warp & 1) * 64, wn = (warp >> 1) * 64;
#pragma unroll
    for (int mi = 0; mi < 4; mi++)
#pragma unroll
        for (int ni = 0; ni < 8; ni++)
#pragma unroll
            for (int r = 0; r < 4; r++) {
                int rl = EPI_ROW(wm, mi, r);
                int cl = EPI_COL(wn, ni, r);
                float corr = 0.f;
#pragma unroll
                for (int h = 0; h < HH; h++) corr += srm[h * 128 + rl] * sA[h * 128 + cl];
                out[(size_t)(m0 + rl) * DD + n0 + cl] =
                    acc[mi][ni][r] * invS * invD2 + g_cb[b * DD + n0 + cl] - invS * corr;
            }
}

// ---------------- host launcher ----------------
extern "C" void kernel_launch(void* const* d_in, const int* in_sizes, int n_in,
                              void* d_out, int out_size)
{
    const float* X  = (const float*)d_in[0];
    const float* Wq = (const float*)d_in[1];
    const float* bq = (const float*)d_in[2];
    const float* Wk = (const float*)d_in[3];
    const float* bk = (const float*)d_in[4];
    const float* Wv = (const float*)d_in[5];
    const float* bv = (const float*)d_in[6];
    const float* Wo = (const float*)d_in[7];
    const float* bo = (const float*)d_in[8];
    float* out = (float*)d_out;
    (void)bk;

    const int SMEM = 3 * STG_H * 2;   // 98304 bytes
    cudaFuncSetAttribute(k_mgemm, cudaFuncAttributeMaxDynamicSharedMemorySize, SMEM);
    cudaFuncSetAttribute(k_G1,    cudaFuncAttributeMaxDynamicSharedMemorySize, SMEM);
    cudaFuncSetAttribute(k_F,     cudaFuncAttributeMaxDynamicSharedMemorySize, SMEM);
    cudaFuncSetAttribute(k_M,     cudaFuncAttributeMaxDynamicSharedMemorySize, SMEM);
    cudaFuncSetAttribute(k_out2,  cudaFuncAttributeMaxDynamicSharedMemorySize, SMEM);

    k_cvt<<<2048, 256>>>(X, Wo);
    k_trw<<<dim3(16, 16, 24), dim3(32, 8)>>>(Wq, Wk, Wv);
    k_trx<<<dim3(16, 32, 8),  dim3(32, 8)>>>();
    k_colsum<<<dim3(8, 16), 256>>>(X);
    k_chat<<<512, 256>>>(Wo, bv, bo);
    k_r<<<dim3(8, 64), 256>>>(bq);
    k_mgemm<<<dim3(4, 4, 16), 128, SMEM>>>();
    k_vbar<<<64, 32>>>();
    k_w1<<<dim3(8, 64), 256>>>(Wv);
    k_w2<<<dim3(8, 64), 256>>>();
    k_rm<<<2048, 128>>>();
    k_G1<<<dim3(4, 4, 8), 128, SMEM>>>();
    k_vx<<<dim3(8, 64), 256>>>();
    k_F<<<dim3(4, 4, 64), 128, SMEM>>>();
    k_ac2<<<dim3(8, 64), 256>>>(Wo);
    k_cb<<<dim3(8, 4), 128>>>();
    k_M<<<dim3(4, 4, 8), 128, SMEM>>>();
    k_out2<<<dim3(64, 4), 128, SMEM>>>(out);
}